// round 7
// baseline (speedup 1.0000x reference)
#include <cuda_runtime.h>
#include <cuda_fp16.h>
#include <math.h>
#include <stdint.h>

#define NN 100000
#define FF 128
#define HH 64
#define CC 16
#define EE 1000000
#define KP128 132
#define KP64 68
#define NB 782   // ceil(NN/128)

// ---------------- scratch ----------------------------------------------------
__device__ __align__(16) __half g_h0h[NN * HH];
__device__ __align__(16) __half g_xmidh[NN * HH];
__device__ __align__(16) __half g_ghhh[NN * 192];
__device__ __align__(16) float  g_x1[NN * HH];
__device__ __align__(16) float  g_x2[NN * HH];

// ---------------- tf32 mma helpers ------------------------------------------
__device__ __forceinline__ uint32_t f2tf(float f) {
    uint32_t u;
    asm("cvt.rna.tf32.f32 %0, %1;" : "=r"(u) : "f"(f));
    return u;
}
__device__ __forceinline__ void mma8(float4& d, uint32_t a0, uint32_t a1,
                                     uint32_t a2, uint32_t a3,
                                     uint32_t b0, uint32_t b1) {
    asm volatile(
        "mma.sync.aligned.m16n8k8.row.col.f32.tf32.tf32.f32 "
        "{%0,%1,%2,%3},{%4,%5,%6,%7},{%8,%9},{%0,%1,%2,%3};"
        : "+f"(d.x), "+f"(d.y), "+f"(d.z), "+f"(d.w)
        : "r"(a0), "r"(a1), "r"(a2), "r"(a3), "r"(b0), "r"(b1));
}
__device__ __forceinline__ float sigf(float x) {
    return 1.f / (1.f + __expf(-x));
}

// ---------------- persistent k_fg: h0 = x@Wf^T+bf ; ghh = h0@Whh^T+bhh -------
// Also zeroes g_x1/g_x2 for the first propagation.
#define FG_A    0                          // 128x132
#define FG_WF   (FG_A + 128 * KP128)       // 64x132
#define FG_WHH  (FG_WF + 64 * KP128)       // 192x68
#define FG_G    (FG_WHH + 192 * KP64)      // 128x68
#define FG_WORDS (FG_G + 128 * KP64)

__global__ __launch_bounds__(1024, 1) void k_fg(const float* __restrict__ x,
                                                const float* __restrict__ Wf,
                                                const float* __restrict__ bf,
                                                const float* __restrict__ Whh,
                                                const float* __restrict__ bhh) {
    extern __shared__ uint32_t sm[];
    uint32_t* sA   = sm + FG_A;
    uint32_t* sWf  = sm + FG_WF;
    uint32_t* sWhh = sm + FG_WHH;
    uint32_t* sG   = sm + FG_G;
    __shared__ float sbf[64];
    __shared__ float sbhh[192];
    int t = threadIdx.x;

    // stage weights ONCE
    for (int i = t; i < 64 * 32; i += 1024) {
        int o = i >> 5, q = i & 31;
        float4 v = *(const float4*)(Wf + o * FF + q * 4);
        uint32_t* d = sWf + o * KP128 + q * 4;
        d[0] = f2tf(v.x); d[1] = f2tf(v.y); d[2] = f2tf(v.z); d[3] = f2tf(v.w);
    }
    for (int i = t; i < 192 * 16; i += 1024) {
        int o = i >> 4, q = i & 15;
        float4 v = *(const float4*)(Whh + o * HH + q * 4);
        uint32_t* d = sWhh + o * KP64 + q * 4;
        d[0] = f2tf(v.x); d[1] = f2tf(v.y); d[2] = f2tf(v.z); d[3] = f2tf(v.w);
    }
    if (t < 64) sbf[t] = bf[t];
    if (t >= 256 && t < 448) sbhh[t - 256] = bhh[t - 256];
    __syncthreads();

    int w = t >> 5, lane = t & 31, g = lane >> 2, tig = lane & 3;
    int r0 = (w & 7) * 16, cw = w >> 3;   // 8 row groups x 4 col groups

    for (int tile = blockIdx.x; tile < NB; tile += gridDim.x) {
        int base = tile * 128;
        {
            float4 z = make_float4(0.f, 0.f, 0.f, 0.f);
            for (int i = t; i < 128 * 16; i += 1024) {
                int node = i >> 4, q = i & 15;
                int n = base + node;
                if (n < NN) {
                    *(float4*)(g_x1 + n * HH + q * 4) = z;
                    *(float4*)(g_x2 + n * HH + q * 4) = z;
                }
            }
        }
        for (int i = t; i < 128 * 32; i += 1024) {
            int node = i >> 5, q = i & 31;
            float4 v = make_float4(0.f, 0.f, 0.f, 0.f);
            if (base + node < NN)
                v = *(const float4*)(x + (base + node) * FF + q * 4);
            uint32_t* d = sA + node * KP128 + q * 4;
            d[0] = f2tf(v.x); d[1] = f2tf(v.y); d[2] = f2tf(v.z); d[3] = f2tf(v.w);
        }
        __syncthreads();

        // GEMM1: h0 = x @ Wf^T  (2 n-tiles per warp)
        {
            int cb = cw * 16;
            float4 acc[2] = {};
#pragma unroll 4
            for (int ks = 0; ks < 16; ks++) {
                int ko = ks * 8;
                uint32_t a0 = sA[(r0 + g) * KP128 + ko + tig];
                uint32_t a1 = sA[(r0 + g + 8) * KP128 + ko + tig];
                uint32_t a2 = sA[(r0 + g) * KP128 + ko + tig + 4];
                uint32_t a3 = sA[(r0 + g + 8) * KP128 + ko + tig + 4];
#pragma unroll
                for (int nt = 0; nt < 2; nt++) {
                    int o = cb + nt * 8 + g;
                    mma8(acc[nt], a0, a1, a2, a3,
                         sWf[o * KP128 + ko + tig], sWf[o * KP128 + ko + tig + 4]);
                }
            }
#pragma unroll
            for (int nt = 0; nt < 2; nt++) {
                int c = cb + nt * 8 + tig * 2;
                int n1 = base + r0 + g, n2 = n1 + 8;
                float v0 = acc[nt].x + sbf[c], v1 = acc[nt].y + sbf[c + 1];
                float v2 = acc[nt].z + sbf[c], v3 = acc[nt].w + sbf[c + 1];
                if (n1 < NN)
                    *(__half2*)(g_h0h + n1 * HH + c) = __floats2half2_rn(v0, v1);
                if (n2 < NN)
                    *(__half2*)(g_h0h + n2 * HH + c) = __floats2half2_rn(v2, v3);
                sG[(r0 + g) * KP64 + c]         = f2tf(v0);
                sG[(r0 + g) * KP64 + c + 1]     = f2tf(v1);
                sG[(r0 + g + 8) * KP64 + c]     = f2tf(v2);
                sG[(r0 + g + 8) * KP64 + c + 1] = f2tf(v3);
            }
        }
        __syncthreads();

        // GEMM2: ghh = h0 @ Whh^T  (6 n-tiles per warp)
        {
            int cb = cw * 48;
            float4 acc[6] = {};
            for (int ks = 0; ks < 8; ks++) {
                int ko = ks * 8;
                uint32_t a0 = sG[(r0 + g) * KP64 + ko + tig];
                uint32_t a1 = sG[(r0 + g + 8) * KP64 + ko + tig];
                uint32_t a2 = sG[(r0 + g) * KP64 + ko + tig + 4];
                uint32_t a3 = sG[(r0 + g + 8) * KP64 + ko + tig + 4];
#pragma unroll
                for (int nt = 0; nt < 6; nt++) {
                    int o = cb + nt * 8 + g;
                    mma8(acc[nt], a0, a1, a2, a3,
                         sWhh[o * KP64 + ko + tig], sWhh[o * KP64 + ko + tig + 4]);
                }
            }
#pragma unroll
            for (int nt = 0; nt < 6; nt++) {
                int c = cb + nt * 8 + tig * 2;
                int n1 = base + r0 + g, n2 = n1 + 8;
                if (n1 < NN)
                    *(__half2*)(g_ghhh + n1 * 192 + c) =
                        __floats2half2_rn(acc[nt].x + sbhh[c], acc[nt].y + sbhh[c + 1]);
                if (n2 < NN)
                    *(__half2*)(g_ghhh + n2 * 192 + c) =
                        __floats2half2_rn(acc[nt].z + sbhh[c], acc[nt].w + sbhh[c + 1]);
            }
        }
        __syncthreads();
    }
}

// ---------------- edge propagation: 8 lanes/edge, LDG.128 + 2x RED.v4 --------
__global__ __launch_bounds__(256) void k_prop(int use_mid,
                                              const int* __restrict__ ei1,
                                              const float* __restrict__ ew1,
                                              const int* __restrict__ ei2,
                                              const float* __restrict__ ew2) {
    const __half* xin = use_mid ? g_xmidh : g_h0h;
    int group = blockIdx.x * 32 + (threadIdx.x >> 3);
    int l8 = threadIdx.x & 7;
    int slot0 = group * 2;   // even; pair never straddles EE

    const int* ei;
    const float* ew;
    float* out;
    int e0;
    if (slot0 < EE) { e0 = slot0;      ei = ei1; ew = ew1; out = g_x1; }
    else            { e0 = slot0 - EE; ei = ei2; ew = ew2; out = g_x2; }

    int s0 = __ldg(ei + e0),      s1 = __ldg(ei + e0 + 1);
    int d0 = __ldg(ei + EE + e0), d1 = __ldg(ei + EE + e0 + 1);
    float w0 = __ldg(ew + e0),    w1 = __ldg(ew + e0 + 1);

    uint4 ua = *(const uint4*)(xin + s0 * HH + l8 * 8);   // 8 halves
    uint4 ub = *(const uint4*)(xin + s1 * HH + l8 * 8);

    float2 a0 = __half22float2(*(__half2*)&ua.x);
    float2 a1 = __half22float2(*(__half2*)&ua.y);
    float2 a2 = __half22float2(*(__half2*)&ua.z);
    float2 a3 = __half22float2(*(__half2*)&ua.w);
    float2 b0 = __half22float2(*(__half2*)&ub.x);
    float2 b1 = __half22float2(*(__half2*)&ub.y);
    float2 b2 = __half22float2(*(__half2*)&ub.z);
    float2 b3 = __half22float2(*(__half2*)&ub.w);

    float* q0 = out + d0 * HH + l8 * 8;
    float* q1 = out + d1 * HH + l8 * 8;
    asm volatile("red.global.add.v4.f32 [%0], {%1, %2, %3, %4};"
                 :: "l"(q0), "f"(a0.x * w0), "f"(a0.y * w0),
                    "f"(a1.x * w0), "f"(a1.y * w0) : "memory");
    asm volatile("red.global.add.v4.f32 [%0], {%1, %2, %3, %4};"
                 :: "l"(q0 + 4), "f"(a2.x * w0), "f"(a2.y * w0),
                    "f"(a3.x * w0), "f"(a3.y * w0) : "memory");
    asm volatile("red.global.add.v4.f32 [%0], {%1, %2, %3, %4};"
                 :: "l"(q1), "f"(b0.x * w1), "f"(b0.y * w1),
                    "f"(b1.x * w1), "f"(b1.y * w1) : "memory");
    asm volatile("red.global.add.v4.f32 [%0], {%1, %2, %3, %4};"
                 :: "l"(q1 + 4), "f"(b2.x * w1), "f"(b2.y * w1),
                    "f"(b3.x * w1), "f"(b3.y * w1) : "memory");
}

// ---------------- persistent fused concat-linear + GRU + out ----------------
#define O_A    0
#define O_WC   (O_A + 128 * KP128)
#define O_WIH  (O_WC + 64 * KP128)
#define O_WL   (O_WIH + 192 * KP64)
#define O_G    (O_WL + 64 * KP64)
#define O_BC   (O_G + 128 * KP64)
#define O_BIH  (O_BC + 64)
#define O_BL   (O_BIH + 192)
#define O_LY   (O_BL + 64)
#define CG_WORDS (O_LY + 128 * 17)

template <bool FINAL>
__global__ __launch_bounds__(1024, 1) void k_congru(
    const float* __restrict__ Wc,  const float* __restrict__ bc,
    const float* __restrict__ Wih, const float* __restrict__ bih,
    const float* __restrict__ Wl,  const float* __restrict__ bl,
    float* __restrict__ dout) {
    extern __shared__ uint32_t sm[];
    uint32_t* sA   = sm + O_A;
    uint32_t* sWc  = sm + O_WC;
    uint32_t* sWih = sm + O_WIH;
    uint32_t* sWl  = sm + O_WL;
    uint32_t* sG   = sm + O_G;
    float* sbc  = (float*)(sm + O_BC);
    float* sbih = (float*)(sm + O_BIH);
    float* sbl  = (float*)(sm + O_BL);
    float* sLY  = (float*)(sm + O_LY);
    const int OC = FINAL ? CC : HH;

    int t = threadIdx.x;

    // stage weights ONCE
    for (int i = t; i < 64 * 32; i += 1024) {
        int o = i >> 5, q = i & 31;
        float4 v = *(const float4*)(Wc + o * FF + q * 4);
        uint32_t* d = sWc + o * KP128 + q * 4;
        d[0] = f2tf(v.x); d[1] = f2tf(v.y); d[2] = f2tf(v.z); d[3] = f2tf(v.w);
    }
    for (int i = t; i < 192 * 16; i += 1024) {
        int o = i >> 4, q = i & 15;
        float4 v = *(const float4*)(Wih + o * HH + q * 4);
        uint32_t* d = sWih + o * KP64 + q * 4;
        d[0] = f2tf(v.x); d[1] = f2tf(v.y); d[2] = f2tf(v.z); d[3] = f2tf(v.w);
    }
    for (int i = t; i < OC * 16; i += 1024) {
        int o = i >> 4, q = i & 15;
        float4 v = *(const float4*)(Wl + o * HH + q * 4);
        uint32_t* d = sWl + o * KP64 + q * 4;
        d[0] = f2tf(v.x); d[1] = f2tf(v.y); d[2] = f2tf(v.z); d[3] = f2tf(v.w);
    }
    if (t < 64)  sbc[t]  = bc[t];
    if (t < 192) sbih[t] = bih[t];
    if (t < OC)  sbl[t]  = bl[t];
    __syncthreads();

    int w = t >> 5, lane = t & 31, g = lane >> 2, tig = lane & 3;
    int r0 = (w & 7) * 16, cw = w >> 3, cb = cw * 16;

    for (int tile = blockIdx.x; tile < NB; tile += gridDim.x) {
        int base = tile * 128;
        for (int i = t; i < 128 * 16; i += 1024) {
            int node = i >> 4, q = i & 15;
            int n = base + node;
            float4 v1 = make_float4(0.f, 0.f, 0.f, 0.f), v2 = v1;
            if (n < NN) {
                v1 = *(const float4*)(g_x1 + n * HH + q * 4);
                v2 = *(const float4*)(g_x2 + n * HH + q * 4);
                if (!FINAL) {
                    // re-zero for the second propagation
                    float4 z = make_float4(0.f, 0.f, 0.f, 0.f);
                    *(float4*)(g_x1 + n * HH + q * 4) = z;
                    *(float4*)(g_x2 + n * HH + q * 4) = z;
                }
            }
            uint32_t* d1 = sA + node * KP128 + q * 4;
            uint32_t* dd2 = d1 + 64;
            d1[0] = f2tf(v1.x); d1[1] = f2tf(v1.y); d1[2] = f2tf(v1.z); d1[3] = f2tf(v1.w);
            dd2[0] = f2tf(v2.x); dd2[1] = f2tf(v2.y); dd2[2] = f2tf(v2.z); dd2[3] = f2tf(v2.w);
        }
        __syncthreads();

        // phase 1: gg = [x1|x2] @ Wc^T + bc  (2 n-tiles per warp)
        {
            float4 acc[2] = {};
#pragma unroll 4
            for (int ks = 0; ks < 16; ks++) {
                int ko = ks * 8;
                uint32_t a0 = sA[(r0 + g) * KP128 + ko + tig];
                uint32_t a1 = sA[(r0 + g + 8) * KP128 + ko + tig];
                uint32_t a2 = sA[(r0 + g) * KP128 + ko + tig + 4];
                uint32_t a3 = sA[(r0 + g + 8) * KP128 + ko + tig + 4];
#pragma unroll
                for (int nt = 0; nt < 2; nt++) {
                    int o = cb + nt * 8 + g;
                    mma8(acc[nt], a0, a1, a2, a3,
                         sWc[o * KP128 + ko + tig], sWc[o * KP128 + ko + tig + 4]);
                }
            }
#pragma unroll
            for (int nt = 0; nt < 2; nt++) {
                int c = cb + nt * 8 + tig * 2;
                sG[(r0 + g) * KP64 + c]         = f2tf(acc[nt].x + sbc[c]);
                sG[(r0 + g) * KP64 + c + 1]     = f2tf(acc[nt].y + sbc[c + 1]);
                sG[(r0 + g + 8) * KP64 + c]     = f2tf(acc[nt].z + sbc[c]);
                sG[(r0 + g + 8) * KP64 + c + 1] = f2tf(acc[nt].w + sbc[c + 1]);
            }
        }
        __syncthreads();

        // phase 2: gi = gg @ Wih^T  (3 gates x 2 n-tiles per warp)
        float4 d2[3][2];
#pragma unroll
        for (int gt = 0; gt < 3; gt++)
#pragma unroll
            for (int nt = 0; nt < 2; nt++)
                d2[gt][nt] = make_float4(0.f, 0.f, 0.f, 0.f);
        for (int ks = 0; ks < 8; ks++) {
            int ko = ks * 8;
            uint32_t a0 = sG[(r0 + g) * KP64 + ko + tig];
            uint32_t a1 = sG[(r0 + g + 8) * KP64 + ko + tig];
            uint32_t a2 = sG[(r0 + g) * KP64 + ko + tig + 4];
            uint32_t a3 = sG[(r0 + g + 8) * KP64 + ko + tig + 4];
#pragma unroll
            for (int gt = 0; gt < 3; gt++)
#pragma unroll
                for (int nt = 0; nt < 2; nt++) {
                    int o = gt * 64 + cb + nt * 8 + g;
                    mma8(d2[gt][nt], a0, a1, a2, a3,
                         sWih[o * KP64 + ko + tig], sWih[o * KP64 + ko + tig + 4]);
                }
        }

        // phase 3: GRU elementwise (ghh, h both fp16)
        float hn[2][4];
#pragma unroll
        for (int nt = 0; nt < 2; nt++) {
            int c = cb + nt * 8 + tig * 2;
#pragma unroll
            for (int half = 0; half < 2; half++) {
                int node = base + r0 + g + half * 8;
                float vr0 = half ? d2[0][nt].z : d2[0][nt].x;
                float vr1 = half ? d2[0][nt].w : d2[0][nt].y;
                float vz0 = half ? d2[1][nt].z : d2[1][nt].x;
                float vz1 = half ? d2[1][nt].w : d2[1][nt].y;
                float vn0 = half ? d2[2][nt].z : d2[2][nt].x;
                float vn1 = half ? d2[2][nt].w : d2[2][nt].y;
                float o0 = 0.f, o1 = 0.f;
                if (node < NN) {
                    float2 gr = __half22float2(*(const __half2*)(g_ghhh + node * 192 + c));
                    float2 gz = __half22float2(*(const __half2*)(g_ghhh + node * 192 + 64 + c));
                    float2 gn = __half22float2(*(const __half2*)(g_ghhh + node * 192 + 128 + c));
                    float2 h  = __half22float2(*(const __half2*)(g_h0h + node * HH + c));
                    float r = sigf(vr0 + sbih[c] + gr.x);
                    float z = sigf(vz0 + sbih[64 + c] + gz.x);
                    float n = tanhf(vn0 + sbih[128 + c] + r * gn.x);
                    o0 = (1.f - z) * n + z * h.x;
                    r = sigf(vr1 + sbih[c + 1] + gr.y);
                    z = sigf(vz1 + sbih[64 + c + 1] + gz.y);
                    n = tanhf(vn1 + sbih[128 + c + 1] + r * gn.y);
                    o1 = (1.f - z) * n + z * h.y;
                }
                hn[nt][half * 2] = o0;
                hn[nt][half * 2 + 1] = o1;
            }
        }
        __syncthreads();
#pragma unroll
        for (int nt = 0; nt < 2; nt++) {
            int c = cb + nt * 8 + tig * 2;
            sG[(r0 + g) * KP64 + c]         = f2tf(hn[nt][0]);
            sG[(r0 + g) * KP64 + c + 1]     = f2tf(hn[nt][1]);
            sG[(r0 + g + 8) * KP64 + c]     = f2tf(hn[nt][2]);
            sG[(r0 + g + 8) * KP64 + c + 1] = f2tf(hn[nt][3]);
        }
        __syncthreads();

        // phase 4: output GEMM
        if (!FINAL) {
            float4 acc[2] = {};
            for (int ks = 0; ks < 8; ks++) {
                int ko = ks * 8;
                uint32_t a0 = sG[(r0 + g) * KP64 + ko + tig];
                uint32_t a1 = sG[(r0 + g + 8) * KP64 + ko + tig];
                uint32_t a2 = sG[(r0 + g) * KP64 + ko + tig + 4];
                uint32_t a3 = sG[(r0 + g + 8) * KP64 + ko + tig + 4];
#pragma unroll
                for (int nt = 0; nt < 2; nt++) {
                    int o = cb + nt * 8 + g;
                    mma8(acc[nt], a0, a1, a2, a3,
                         sWl[o * KP64 + ko + tig], sWl[o * KP64 + ko + tig + 4]);
                }
            }
#pragma unroll
            for (int nt = 0; nt < 2; nt++) {
                int c = cb + nt * 8 + tig * 2;
                int n1 = base + r0 + g, n2 = n1 + 8;
                if (n1 < NN)
                    *(__half2*)(g_xmidh + n1 * HH + c) =
                        __floats2half2_rn(acc[nt].x + sbl[c], acc[nt].y + sbl[c + 1]);
                if (n2 < NN)
                    *(__half2*)(g_xmidh + n2 * HH + c) =
                        __floats2half2_rn(acc[nt].z + sbl[c], acc[nt].w + sbl[c + 1]);
            }
        } else {
            if (cw < 2) {
                float4 acc = make_float4(0.f, 0.f, 0.f, 0.f);
                int c0f = cw * 8;
                for (int ks = 0; ks < 8; ks++) {
                    int ko = ks * 8;
                    uint32_t a0 = sG[(r0 + g) * KP64 + ko + tig];
                    uint32_t a1 = sG[(r0 + g + 8) * KP64 + ko + tig];
                    uint32_t a2 = sG[(r0 + g) * KP64 + ko + tig + 4];
                    uint32_t a3 = sG[(r0 + g + 8) * KP64 + ko + tig + 4];
                    int o = c0f + g;
                    mma8(acc, a0, a1, a2, a3,
                         sWl[o * KP64 + ko + tig], sWl[o * KP64 + ko + tig + 4]);
                }
                int c = c0f + tig * 2;
                sLY[(r0 + g) * 17 + c]         = acc.x + sbl[c];
                sLY[(r0 + g) * 17 + c + 1]     = acc.y + sbl[c + 1];
                sLY[(r0 + g + 8) * 17 + c]     = acc.z + sbl[c];
                sLY[(r0 + g + 8) * 17 + c + 1] = acc.w + sbl[c + 1];
            }
            __syncthreads();
            if (t < 128) {
                int node = base + t;
                if (node < NN) {
                    float m = -1e30f;
#pragma unroll
                    for (int cc = 0; cc < 16; cc++) m = fmaxf(m, sLY[t * 17 + cc]);
                    float s = 0.f;
#pragma unroll
                    for (int cc = 0; cc < 16; cc++) s += expf(sLY[t * 17 + cc] - m);
                    float l = m + logf(s);
#pragma unroll
                    for (int cc = 0; cc < 16; cc++)
                        dout[node * CC + cc] = sLY[t * 17 + cc] - l;
                }
            }
        }
        __syncthreads();
    }
}

// ---------------- launch -----------------------------------------------------
extern "C" void kernel_launch(void* const* d_in, const int* in_sizes, int n_in,
                              void* d_out, int out_size) {
    const float* x       = (const float*)d_in[0];
    const int*   ei      = (const int*)  d_in[1];
    const float* ew      = (const float*)d_in[2];
    const int*   eir     = (const int*)  d_in[3];
    const float* ewr     = (const float*)d_in[4];
    const float* W_first = (const float*)d_in[5];
    const float* b_first = (const float*)d_in[6];
    const float* W_con1  = (const float*)d_in[7];
    const float* b_con1  = (const float*)d_in[8];
    const float* W_con2  = (const float*)d_in[9];
    const float* b_con2  = (const float*)d_in[10];
    const float* W_lin1  = (const float*)d_in[11];
    const float* b_lin1  = (const float*)d_in[12];
    const float* W_out   = (const float*)d_in[13];
    const float* b_out   = (const float*)d_in[14];
    const float* W_ih    = (const float*)d_in[15];
    const float* W_hh    = (const float*)d_in[16];
    const float* b_ih    = (const float*)d_in[17];
    const float* b_hh    = (const float*)d_in[18];
    float* out = (float*)d_out;

    const int SM_FG = FG_WORDS * 4;
    const int SM_CG = CG_WORDS * 4;

    cudaFuncSetAttribute(k_fg, cudaFuncAttributeMaxDynamicSharedMemorySize, SM_FG);
    cudaFuncSetAttribute(k_congru<false>,
                         cudaFuncAttributeMaxDynamicSharedMemorySize, SM_CG);
    cudaFuncSetAttribute(k_congru<true>,
                         cudaFuncAttributeMaxDynamicSharedMemorySize, SM_CG);

    const int PERS = 148;                     // persistent: 1 CTA per SM
    const int PROP_BLOCKS = (2 * EE) / 64;    // 2 edges per 8-lane group

    k_fg<<<PERS, 1024, SM_FG>>>(x, W_first, b_first, W_hh, b_hh);
    k_prop<<<PROP_BLOCKS, 256>>>(0, ei, ew, eir, ewr);
    k_congru<false><<<PERS, 1024, SM_CG>>>(W_con1, b_con1, W_ih, b_ih,
                                           W_lin1, b_lin1, nullptr);
    k_prop<<<PROP_BLOCKS, 256>>>(1, ei, ew, eir, ewr);
    k_congru<true><<<PERS, 1024, SM_CG>>>(W_con2, b_con2, W_ih, b_ih,
                                          W_out, b_out, out);
}

// round 8
// speedup vs baseline: 1.1582x; 1.1582x over previous
#include <cuda_runtime.h>
#include <cuda_fp16.h>
#include <math.h>
#include <stdint.h>

#define NN 100000
#define FF 128
#define HH 64
#define CC 16
#define EE 1000000
#define KP128 132
#define KP64 68
#define NB 782   // ceil(NN/128)

// ---------------- scratch ----------------------------------------------------
__device__ __align__(16) __half g_h0h[NN * HH];
__device__ __align__(16) __half g_xmidh[NN * HH];
__device__ __align__(16) __half g_ghhh[NN * 192];
__device__ __align__(16) float  g_x1[NN * HH];
__device__ __align__(16) float  g_x2[NN * HH];

// ---------------- tf32 mma helpers ------------------------------------------
__device__ __forceinline__ uint32_t f2tf(float f) {
    uint32_t u;
    asm("cvt.rna.tf32.f32 %0, %1;" : "=r"(u) : "f"(f));
    return u;
}
__device__ __forceinline__ void mma8(float4& d, uint32_t a0, uint32_t a1,
                                     uint32_t a2, uint32_t a3,
                                     uint32_t b0, uint32_t b1) {
    asm volatile(
        "mma.sync.aligned.m16n8k8.row.col.f32.tf32.tf32.f32 "
        "{%0,%1,%2,%3},{%4,%5,%6,%7},{%8,%9},{%0,%1,%2,%3};"
        : "+f"(d.x), "+f"(d.y), "+f"(d.z), "+f"(d.w)
        : "r"(a0), "r"(a1), "r"(a2), "r"(a3), "r"(b0), "r"(b1));
}
__device__ __forceinline__ float sigf(float x) {
    return 1.f / (1.f + __expf(-x));
}

// ---------------- persistent k_fg: h0 = x@Wf^T+bf ; ghh = h0@Whh^T+bhh -------
// Also zeroes g_x1/g_x2 for the first propagation.
#define FG_A    0                          // 128x132
#define FG_WF   (FG_A + 128 * KP128)       // 64x132
#define FG_WHH  (FG_WF + 64 * KP128)       // 192x68
#define FG_G    (FG_WHH + 192 * KP64)      // 128x68
#define FG_WORDS (FG_G + 128 * KP64)

__global__ __launch_bounds__(1024, 1) void k_fg(const float* __restrict__ x,
                                                const float* __restrict__ Wf,
                                                const float* __restrict__ bf,
                                                const float* __restrict__ Whh,
                                                const float* __restrict__ bhh) {
    extern __shared__ uint32_t sm[];
    uint32_t* sA   = sm + FG_A;
    uint32_t* sWf  = sm + FG_WF;
    uint32_t* sWhh = sm + FG_WHH;
    uint32_t* sG   = sm + FG_G;
    __shared__ float sbf[64];
    __shared__ float sbhh[192];
    int t = threadIdx.x;

    // stage weights ONCE
    for (int i = t; i < 64 * 32; i += 1024) {
        int o = i >> 5, q = i & 31;
        float4 v = *(const float4*)(Wf + o * FF + q * 4);
        uint32_t* d = sWf + o * KP128 + q * 4;
        d[0] = f2tf(v.x); d[1] = f2tf(v.y); d[2] = f2tf(v.z); d[3] = f2tf(v.w);
    }
    for (int i = t; i < 192 * 16; i += 1024) {
        int o = i >> 4, q = i & 15;
        float4 v = *(const float4*)(Whh + o * HH + q * 4);
        uint32_t* d = sWhh + o * KP64 + q * 4;
        d[0] = f2tf(v.x); d[1] = f2tf(v.y); d[2] = f2tf(v.z); d[3] = f2tf(v.w);
    }
    if (t < 64) sbf[t] = bf[t];
    if (t >= 256 && t < 448) sbhh[t - 256] = bhh[t - 256];
    __syncthreads();

    int w = t >> 5, lane = t & 31, g = lane >> 2, tig = lane & 3;
    int r0 = (w & 7) * 16, cw = w >> 3;   // 8 row groups x 4 col groups

    for (int tile = blockIdx.x; tile < NB; tile += gridDim.x) {
        int base = tile * 128;
        {
            float4 z = make_float4(0.f, 0.f, 0.f, 0.f);
            for (int i = t; i < 128 * 16; i += 1024) {
                int node = i >> 4, q = i & 15;
                int n = base + node;
                if (n < NN) {
                    *(float4*)(g_x1 + n * HH + q * 4) = z;
                    *(float4*)(g_x2 + n * HH + q * 4) = z;
                }
            }
        }
        for (int i = t; i < 128 * 32; i += 1024) {
            int node = i >> 5, q = i & 31;
            float4 v = make_float4(0.f, 0.f, 0.f, 0.f);
            if (base + node < NN)
                v = *(const float4*)(x + (base + node) * FF + q * 4);
            uint32_t* d = sA + node * KP128 + q * 4;
            d[0] = f2tf(v.x); d[1] = f2tf(v.y); d[2] = f2tf(v.z); d[3] = f2tf(v.w);
        }
        __syncthreads();

        // GEMM1: h0 = x @ Wf^T  (2 n-tiles per warp)
        {
            int cb = cw * 16;
            float4 acc[2] = {};
#pragma unroll 4
            for (int ks = 0; ks < 16; ks++) {
                int ko = ks * 8;
                uint32_t a0 = sA[(r0 + g) * KP128 + ko + tig];
                uint32_t a1 = sA[(r0 + g + 8) * KP128 + ko + tig];
                uint32_t a2 = sA[(r0 + g) * KP128 + ko + tig + 4];
                uint32_t a3 = sA[(r0 + g + 8) * KP128 + ko + tig + 4];
#pragma unroll
                for (int nt = 0; nt < 2; nt++) {
                    int o = cb + nt * 8 + g;
                    mma8(acc[nt], a0, a1, a2, a3,
                         sWf[o * KP128 + ko + tig], sWf[o * KP128 + ko + tig + 4]);
                }
            }
#pragma unroll
            for (int nt = 0; nt < 2; nt++) {
                int c = cb + nt * 8 + tig * 2;
                int n1 = base + r0 + g, n2 = n1 + 8;
                float v0 = acc[nt].x + sbf[c], v1 = acc[nt].y + sbf[c + 1];
                float v2 = acc[nt].z + sbf[c], v3 = acc[nt].w + sbf[c + 1];
                if (n1 < NN)
                    *(__half2*)(g_h0h + n1 * HH + c) = __floats2half2_rn(v0, v1);
                if (n2 < NN)
                    *(__half2*)(g_h0h + n2 * HH + c) = __floats2half2_rn(v2, v3);
                sG[(r0 + g) * KP64 + c]         = f2tf(v0);
                sG[(r0 + g) * KP64 + c + 1]     = f2tf(v1);
                sG[(r0 + g + 8) * KP64 + c]     = f2tf(v2);
                sG[(r0 + g + 8) * KP64 + c + 1] = f2tf(v3);
            }
        }
        __syncthreads();

        // GEMM2: ghh = h0 @ Whh^T  (6 n-tiles per warp)
        {
            int cb = cw * 48;
            float4 acc[6] = {};
            for (int ks = 0; ks < 8; ks++) {
                int ko = ks * 8;
                uint32_t a0 = sG[(r0 + g) * KP64 + ko + tig];
                uint32_t a1 = sG[(r0 + g + 8) * KP64 + ko + tig];
                uint32_t a2 = sG[(r0 + g) * KP64 + ko + tig + 4];
                uint32_t a3 = sG[(r0 + g + 8) * KP64 + ko + tig + 4];
#pragma unroll
                for (int nt = 0; nt < 6; nt++) {
                    int o = cb + nt * 8 + g;
                    mma8(acc[nt], a0, a1, a2, a3,
                         sWhh[o * KP64 + ko + tig], sWhh[o * KP64 + ko + tig + 4]);
                }
            }
#pragma unroll
            for (int nt = 0; nt < 6; nt++) {
                int c = cb + nt * 8 + tig * 2;
                int n1 = base + r0 + g, n2 = n1 + 8;
                if (n1 < NN)
                    *(__half2*)(g_ghhh + n1 * 192 + c) =
                        __floats2half2_rn(acc[nt].x + sbhh[c], acc[nt].y + sbhh[c + 1]);
                if (n2 < NN)
                    *(__half2*)(g_ghhh + n2 * 192 + c) =
                        __floats2half2_rn(acc[nt].z + sbhh[c], acc[nt].w + sbhh[c + 1]);
            }
        }
        __syncthreads();
    }
}

// ---------------- edge propagation: 16 lanes/edge, contiguous RED.v4 ---------
// (R6-proven pattern: one RED per thread, warp covers contiguous 256B rows)
__global__ __launch_bounds__(256) void k_prop(int use_mid,
                                              const int* __restrict__ ei1,
                                              const float* __restrict__ ew1,
                                              const int* __restrict__ ei2,
                                              const float* __restrict__ ew2) {
    const __half* xin = use_mid ? g_xmidh : g_h0h;
    int group = blockIdx.x * 16 + (threadIdx.x >> 4);
    int l16 = threadIdx.x & 15;
    int slot0 = group * 2;   // even; pair never straddles EE

    const int* ei;
    const float* ew;
    float* out;
    int e0;
    if (slot0 < EE) { e0 = slot0;      ei = ei1; ew = ew1; out = g_x1; }
    else            { e0 = slot0 - EE; ei = ei2; ew = ew2; out = g_x2; }

    int s0 = __ldg(ei + e0),      s1 = __ldg(ei + e0 + 1);
    int d0 = __ldg(ei + EE + e0), d1 = __ldg(ei + EE + e0 + 1);
    float w0 = __ldg(ew + e0),    w1 = __ldg(ew + e0 + 1);

    const __half2* p0 = (const __half2*)(xin + s0 * HH + l16 * 4);
    const __half2* p1 = (const __half2*)(xin + s1 * HH + l16 * 4);
    __half2 a0 = p0[0], a1 = p0[1];
    __half2 b0 = p1[0], b1 = p1[1];

    float2 f0 = __half22float2(a0), f1 = __half22float2(a1);
    float2 g0 = __half22float2(b0), g1 = __half22float2(b1);

    float* q0 = out + d0 * HH + l16 * 4;
    float* q1 = out + d1 * HH + l16 * 4;
    asm volatile("red.global.add.v4.f32 [%0], {%1, %2, %3, %4};"
                 :: "l"(q0), "f"(f0.x * w0), "f"(f0.y * w0),
                    "f"(f1.x * w0), "f"(f1.y * w0) : "memory");
    asm volatile("red.global.add.v4.f32 [%0], {%1, %2, %3, %4};"
                 :: "l"(q1), "f"(g0.x * w1), "f"(g0.y * w1),
                    "f"(g1.x * w1), "f"(g1.y * w1) : "memory");
}

// ---------------- persistent fused concat-linear + GRU + out ----------------
#define O_A    0
#define O_WC   (O_A + 128 * KP128)
#define O_WIH  (O_WC + 64 * KP128)
#define O_WL   (O_WIH + 192 * KP64)
#define O_G    (O_WL + 64 * KP64)
#define O_BC   (O_G + 128 * KP64)
#define O_BIH  (O_BC + 64)
#define O_BL   (O_BIH + 192)
#define O_LY   (O_BL + 64)
#define CG_WORDS (O_LY + 128 * 17)

template <bool FINAL>
__global__ __launch_bounds__(1024, 1) void k_congru(
    const float* __restrict__ Wc,  const float* __restrict__ bc,
    const float* __restrict__ Wih, const float* __restrict__ bih,
    const float* __restrict__ Wl,  const float* __restrict__ bl,
    float* __restrict__ dout) {
    extern __shared__ uint32_t sm[];
    uint32_t* sA   = sm + O_A;
    uint32_t* sWc  = sm + O_WC;
    uint32_t* sWih = sm + O_WIH;
    uint32_t* sWl  = sm + O_WL;
    uint32_t* sG   = sm + O_G;
    float* sbc  = (float*)(sm + O_BC);
    float* sbih = (float*)(sm + O_BIH);
    float* sbl  = (float*)(sm + O_BL);
    float* sLY  = (float*)(sm + O_LY);
    const int OC = FINAL ? CC : HH;

    int t = threadIdx.x;

    // stage weights ONCE
    for (int i = t; i < 64 * 32; i += 1024) {
        int o = i >> 5, q = i & 31;
        float4 v = *(const float4*)(Wc + o * FF + q * 4);
        uint32_t* d = sWc + o * KP128 + q * 4;
        d[0] = f2tf(v.x); d[1] = f2tf(v.y); d[2] = f2tf(v.z); d[3] = f2tf(v.w);
    }
    for (int i = t; i < 192 * 16; i += 1024) {
        int o = i >> 4, q = i & 15;
        float4 v = *(const float4*)(Wih + o * HH + q * 4);
        uint32_t* d = sWih + o * KP64 + q * 4;
        d[0] = f2tf(v.x); d[1] = f2tf(v.y); d[2] = f2tf(v.z); d[3] = f2tf(v.w);
    }
    for (int i = t; i < OC * 16; i += 1024) {
        int o = i >> 4, q = i & 15;
        float4 v = *(const float4*)(Wl + o * HH + q * 4);
        uint32_t* d = sWl + o * KP64 + q * 4;
        d[0] = f2tf(v.x); d[1] = f2tf(v.y); d[2] = f2tf(v.z); d[3] = f2tf(v.w);
    }
    if (t < 64)  sbc[t]  = bc[t];
    if (t < 192) sbih[t] = bih[t];
    if (t < OC)  sbl[t]  = bl[t];
    __syncthreads();

    int w = t >> 5, lane = t & 31, g = lane >> 2, tig = lane & 3;
    int r0 = (w & 7) * 16, cw = w >> 3, cb = cw * 16;

    for (int tile = blockIdx.x; tile < NB; tile += gridDim.x) {
        int base = tile * 128;
        for (int i = t; i < 128 * 16; i += 1024) {
            int node = i >> 4, q = i & 15;
            int n = base + node;
            float4 v1 = make_float4(0.f, 0.f, 0.f, 0.f), v2 = v1;
            if (n < NN) {
                v1 = *(const float4*)(g_x1 + n * HH + q * 4);
                v2 = *(const float4*)(g_x2 + n * HH + q * 4);
                if (!FINAL) {
                    float4 z = make_float4(0.f, 0.f, 0.f, 0.f);
                    *(float4*)(g_x1 + n * HH + q * 4) = z;
                    *(float4*)(g_x2 + n * HH + q * 4) = z;
                }
            }
            uint32_t* d1 = sA + node * KP128 + q * 4;
            uint32_t* dd2 = d1 + 64;
            d1[0] = f2tf(v1.x); d1[1] = f2tf(v1.y); d1[2] = f2tf(v1.z); d1[3] = f2tf(v1.w);
            dd2[0] = f2tf(v2.x); dd2[1] = f2tf(v2.y); dd2[2] = f2tf(v2.z); dd2[3] = f2tf(v2.w);
        }
        __syncthreads();

        // phase 1: gg = [x1|x2] @ Wc^T + bc  (2 n-tiles per warp)
        {
            float4 acc[2] = {};
#pragma unroll 4
            for (int ks = 0; ks < 16; ks++) {
                int ko = ks * 8;
                uint32_t a0 = sA[(r0 + g) * KP128 + ko + tig];
                uint32_t a1 = sA[(r0 + g + 8) * KP128 + ko + tig];
                uint32_t a2 = sA[(r0 + g) * KP128 + ko + tig + 4];
                uint32_t a3 = sA[(r0 + g + 8) * KP128 + ko + tig + 4];
#pragma unroll
                for (int nt = 0; nt < 2; nt++) {
                    int o = cb + nt * 8 + g;
                    mma8(acc[nt], a0, a1, a2, a3,
                         sWc[o * KP128 + ko + tig], sWc[o * KP128 + ko + tig + 4]);
                }
            }
#pragma unroll
            for (int nt = 0; nt < 2; nt++) {
                int c = cb + nt * 8 + tig * 2;
                sG[(r0 + g) * KP64 + c]         = f2tf(acc[nt].x + sbc[c]);
                sG[(r0 + g) * KP64 + c + 1]     = f2tf(acc[nt].y + sbc[c + 1]);
                sG[(r0 + g + 8) * KP64 + c]     = f2tf(acc[nt].z + sbc[c]);
                sG[(r0 + g + 8) * KP64 + c + 1] = f2tf(acc[nt].w + sbc[c + 1]);
            }
        }
        __syncthreads();

        // phase 2: gi = gg @ Wih^T  (3 gates x 2 n-tiles per warp)
        float4 d2[3][2];
#pragma unroll
        for (int gt = 0; gt < 3; gt++)
#pragma unroll
            for (int nt = 0; nt < 2; nt++)
                d2[gt][nt] = make_float4(0.f, 0.f, 0.f, 0.f);
        for (int ks = 0; ks < 8; ks++) {
            int ko = ks * 8;
            uint32_t a0 = sG[(r0 + g) * KP64 + ko + tig];
            uint32_t a1 = sG[(r0 + g + 8) * KP64 + ko + tig];
            uint32_t a2 = sG[(r0 + g) * KP64 + ko + tig + 4];
            uint32_t a3 = sG[(r0 + g + 8) * KP64 + ko + tig + 4];
#pragma unroll
            for (int gt = 0; gt < 3; gt++)
#pragma unroll
                for (int nt = 0; nt < 2; nt++) {
                    int o = gt * 64 + cb + nt * 8 + g;
                    mma8(d2[gt][nt], a0, a1, a2, a3,
                         sWih[o * KP64 + ko + tig], sWih[o * KP64 + ko + tig + 4]);
                }
        }

        // phase 3: GRU elementwise (ghh, h both fp16)
        float hn[2][4];
#pragma unroll
        for (int nt = 0; nt < 2; nt++) {
            int c = cb + nt * 8 + tig * 2;
#pragma unroll
            for (int half = 0; half < 2; half++) {
                int node = base + r0 + g + half * 8;
                float vr0 = half ? d2[0][nt].z : d2[0][nt].x;
                float vr1 = half ? d2[0][nt].w : d2[0][nt].y;
                float vz0 = half ? d2[1][nt].z : d2[1][nt].x;
                float vz1 = half ? d2[1][nt].w : d2[1][nt].y;
                float vn0 = half ? d2[2][nt].z : d2[2][nt].x;
                float vn1 = half ? d2[2][nt].w : d2[2][nt].y;
                float o0 = 0.f, o1 = 0.f;
                if (node < NN) {
                    float2 gr = __half22float2(*(const __half2*)(g_ghhh + node * 192 + c));
                    float2 gz = __half22float2(*(const __half2*)(g_ghhh + node * 192 + 64 + c));
                    float2 gn = __half22float2(*(const __half2*)(g_ghhh + node * 192 + 128 + c));
                    float2 h  = __half22float2(*(const __half2*)(g_h0h + node * HH + c));
                    float r = sigf(vr0 + sbih[c] + gr.x);
                    float z = sigf(vz0 + sbih[64 + c] + gz.x);
                    float n = tanhf(vn0 + sbih[128 + c] + r * gn.x);
                    o0 = (1.f - z) * n + z * h.x;
                    r = sigf(vr1 + sbih[c + 1] + gr.y);
                    z = sigf(vz1 + sbih[64 + c + 1] + gz.y);
                    n = tanhf(vn1 + sbih[128 + c + 1] + r * gn.y);
                    o1 = (1.f - z) * n + z * h.y;
                }
                hn[nt][half * 2] = o0;
                hn[nt][half * 2 + 1] = o1;
            }
        }
        __syncthreads();
#pragma unroll
        for (int nt = 0; nt < 2; nt++) {
            int c = cb + nt * 8 + tig * 2;
            sG[(r0 + g) * KP64 + c]         = f2tf(hn[nt][0]);
            sG[(r0 + g) * KP64 + c + 1]     = f2tf(hn[nt][1]);
            sG[(r0 + g + 8) * KP64 + c]     = f2tf(hn[nt][2]);
            sG[(r0 + g + 8) * KP64 + c + 1] = f2tf(hn[nt][3]);
        }
        __syncthreads();

        // phase 4: output GEMM
        if (!FINAL) {
            float4 acc[2] = {};
            for (int ks = 0; ks < 8; ks++) {
                int ko = ks * 8;
                uint32_t a0 = sG[(r0 + g) * KP64 + ko + tig];
                uint32_t a1 = sG[(r0 + g + 8) * KP64 + ko + tig];
                uint32_t a2 = sG[(r0 + g) * KP64 + ko + tig + 4];
                uint32_t a3 = sG[(r0 + g + 8) * KP64 + ko + tig + 4];
#pragma unroll
                for (int nt = 0; nt < 2; nt++) {
                    int o = cb + nt * 8 + g;
                    mma8(acc[nt], a0, a1, a2, a3,
                         sWl[o * KP64 + ko + tig], sWl[o * KP64 + ko + tig + 4]);
                }
            }
#pragma unroll
            for (int nt = 0; nt < 2; nt++) {
                int c = cb + nt * 8 + tig * 2;
                int n1 = base + r0 + g, n2 = n1 + 8;
                if (n1 < NN)
                    *(__half2*)(g_xmidh + n1 * HH + c) =
                        __floats2half2_rn(acc[nt].x + sbl[c], acc[nt].y + sbl[c + 1]);
                if (n2 < NN)
                    *(__half2*)(g_xmidh + n2 * HH + c) =
                        __floats2half2_rn(acc[nt].z + sbl[c], acc[nt].w + sbl[c + 1]);
            }
        } else {
            if (cw < 2) {
                float4 acc = make_float4(0.f, 0.f, 0.f, 0.f);
                int c0f = cw * 8;
                for (int ks = 0; ks < 8; ks++) {
                    int ko = ks * 8;
                    uint32_t a0 = sG[(r0 + g) * KP64 + ko + tig];
                    uint32_t a1 = sG[(r0 + g + 8) * KP64 + ko + tig];
                    uint32_t a2 = sG[(r0 + g) * KP64 + ko + tig + 4];
                    uint32_t a3 = sG[(r0 + g + 8) * KP64 + ko + tig + 4];
                    int o = c0f + g;
                    mma8(acc, a0, a1, a2, a3,
                         sWl[o * KP64 + ko + tig], sWl[o * KP64 + ko + tig + 4]);
                }
                int c = c0f + tig * 2;
                sLY[(r0 + g) * 17 + c]         = acc.x + sbl[c];
                sLY[(r0 + g) * 17 + c + 1]     = acc.y + sbl[c + 1];
                sLY[(r0 + g + 8) * 17 + c]     = acc.z + sbl[c];
                sLY[(r0 + g + 8) * 17 + c + 1] = acc.w + sbl[c + 1];
            }
            __syncthreads();
            if (t < 128) {
                int node = base + t;
                if (node < NN) {
                    float m = -1e30f;
#pragma unroll
                    for (int cc = 0; cc < 16; cc++) m = fmaxf(m, sLY[t * 17 + cc]);
                    float s = 0.f;
#pragma unroll
                    for (int cc = 0; cc < 16; cc++) s += expf(sLY[t * 17 + cc] - m);
                    float l = m + logf(s);
#pragma unroll
                    for (int cc = 0; cc < 16; cc++)
                        dout[node * CC + cc] = sLY[t * 17 + cc] - l;
                }
            }
        }
        __syncthreads();
    }
}

// ---------------- launch -----------------------------------------------------
extern "C" void kernel_launch(void* const* d_in, const int* in_sizes, int n_in,
                              void* d_out, int out_size) {
    const float* x       = (const float*)d_in[0];
    const int*   ei      = (const int*)  d_in[1];
    const float* ew      = (const float*)d_in[2];
    const int*   eir     = (const int*)  d_in[3];
    const float* ewr     = (const float*)d_in[4];
    const float* W_first = (const float*)d_in[5];
    const float* b_first = (const float*)d_in[6];
    const float* W_con1  = (const float*)d_in[7];
    const float* b_con1  = (const float*)d_in[8];
    const float* W_con2  = (const float*)d_in[9];
    const float* b_con2  = (const float*)d_in[10];
    const float* W_lin1  = (const float*)d_in[11];
    const float* b_lin1  = (const float*)d_in[12];
    const float* W_out   = (const float*)d_in[13];
    const float* b_out   = (const float*)d_in[14];
    const float* W_ih    = (const float*)d_in[15];
    const float* W_hh    = (const float*)d_in[16];
    const float* b_ih    = (const float*)d_in[17];
    const float* b_hh    = (const float*)d_in[18];
    float* out = (float*)d_out;

    const int SM_FG = FG_WORDS * 4;
    const int SM_CG = CG_WORDS * 4;

    cudaFuncSetAttribute(k_fg, cudaFuncAttributeMaxDynamicSharedMemorySize, SM_FG);
    cudaFuncSetAttribute(k_congru<false>,
                         cudaFuncAttributeMaxDynamicSharedMemorySize, SM_CG);
    cudaFuncSetAttribute(k_congru<true>,
                         cudaFuncAttributeMaxDynamicSharedMemorySize, SM_CG);

    const int PERS = 148;                     // persistent: 1 CTA per SM
    const int PROP_BLOCKS = (2 * EE) / 32;    // 2 edges per 16-lane group

    k_fg<<<PERS, 1024, SM_FG>>>(x, W_first, b_first, W_hh, b_hh);
    k_prop<<<PROP_BLOCKS, 256>>>(0, ei, ew, eir, ewr);
    k_congru<false><<<PERS, 1024, SM_CG>>>(W_con1, b_con1, W_ih, b_ih,
                                           W_lin1, b_lin1, nullptr);
    k_prop<<<PROP_BLOCKS, 256>>>(1, ei, ew, eir, ewr);
    k_congru<true><<<PERS, 1024, SM_CG>>>(W_con2, b_con2, W_ih, b_ih,
                                          W_out, b_out, out);
}

// round 9
// speedup vs baseline: 1.3116x; 1.1324x over previous
#include <cuda_runtime.h>
#include <cuda_fp16.h>
#include <math.h>
#include <stdint.h>

#define NN 100000
#define FF 128
#define HH 64
#define CC 16
#define EE 1000000
#define KP128 132
#define KP64 68
#define NB 782   // ceil(NN/128)

// ---------------- scratch ----------------------------------------------------
__device__ __align__(16) __half g_h0h[NN * HH];
__device__ __align__(16) __half g_xmidh[NN * HH];
__device__ __align__(16) __half g_ghhh[NN * 192];
__device__ __align__(16) float  g_x1[NN * HH];
__device__ __align__(16) float  g_x2[NN * HH];

// ---------------- tf32 mma helpers ------------------------------------------
__device__ __forceinline__ uint32_t f2tf(float f) {
    uint32_t u;
    asm("cvt.rna.tf32.f32 %0, %1;" : "=r"(u) : "f"(f));
    return u;
}
__device__ __forceinline__ void mma8(float4& d, uint32_t a0, uint32_t a1,
                                     uint32_t a2, uint32_t a3,
                                     uint32_t b0, uint32_t b1) {
    asm volatile(
        "mma.sync.aligned.m16n8k8.row.col.f32.tf32.tf32.f32 "
        "{%0,%1,%2,%3},{%4,%5,%6,%7},{%8,%9},{%0,%1,%2,%3};"
        : "+f"(d.x), "+f"(d.y), "+f"(d.z), "+f"(d.w)
        : "r"(a0), "r"(a1), "r"(a2), "r"(a3), "r"(b0), "r"(b1));
}
__device__ __forceinline__ float sigf(float x) {
    return 1.f / (1.f + __expf(-x));
}

// ---------------- zero the two scatter buffers (throughput-shaped) -----------
__global__ void k_zero() {
    const int tot = NN * HH / 4;
    float4 z = make_float4(0.f, 0.f, 0.f, 0.f);
    for (int i = blockIdx.x * blockDim.x + threadIdx.x; i < tot;
         i += gridDim.x * blockDim.x) {
        reinterpret_cast<float4*>(g_x1)[i] = z;
        reinterpret_cast<float4*>(g_x2)[i] = z;
    }
}

// ---------------- persistent k_fg: h0 = x@Wf^T+bf ; ghh = h0@Whh^T+bhh -------
#define FG_A    0                          // 128x132
#define FG_WF   (FG_A + 128 * KP128)       // 64x132
#define FG_WHH  (FG_WF + 64 * KP128)       // 192x68
#define FG_G    (FG_WHH + 192 * KP64)      // 128x68
#define FG_WORDS (FG_G + 128 * KP64)

__global__ __launch_bounds__(1024, 1) void k_fg(const float* __restrict__ x,
                                                const float* __restrict__ Wf,
                                                const float* __restrict__ bf,
                                                const float* __restrict__ Whh,
                                                const float* __restrict__ bhh) {
    extern __shared__ uint32_t sm[];
    uint32_t* sA   = sm + FG_A;
    uint32_t* sWf  = sm + FG_WF;
    uint32_t* sWhh = sm + FG_WHH;
    uint32_t* sG   = sm + FG_G;
    __shared__ float sbf[64];
    __shared__ float sbhh[192];
    int t = threadIdx.x;

    // stage weights ONCE
    for (int i = t; i < 64 * 32; i += 1024) {
        int o = i >> 5, q = i & 31;
        float4 v = *(const float4*)(Wf + o * FF + q * 4);
        uint32_t* d = sWf + o * KP128 + q * 4;
        d[0] = f2tf(v.x); d[1] = f2tf(v.y); d[2] = f2tf(v.z); d[3] = f2tf(v.w);
    }
    for (int i = t; i < 192 * 16; i += 1024) {
        int o = i >> 4, q = i & 15;
        float4 v = *(const float4*)(Whh + o * HH + q * 4);
        uint32_t* d = sWhh + o * KP64 + q * 4;
        d[0] = f2tf(v.x); d[1] = f2tf(v.y); d[2] = f2tf(v.z); d[3] = f2tf(v.w);
    }
    if (t < 64) sbf[t] = bf[t];
    if (t >= 256 && t < 448) sbhh[t - 256] = bhh[t - 256];
    __syncthreads();

    int w = t >> 5, lane = t & 31, g = lane >> 2, tig = lane & 3;
    int r0 = (w & 7) * 16, cw = w >> 3;   // 8 row groups x 4 col groups

    for (int tile = blockIdx.x; tile < NB; tile += gridDim.x) {
        int base = tile * 128;
        for (int i = t; i < 128 * 32; i += 1024) {
            int node = i >> 5, q = i & 31;
            float4 v = make_float4(0.f, 0.f, 0.f, 0.f);
            if (base + node < NN)
                v = *(const float4*)(x + (base + node) * FF + q * 4);
            uint32_t* d = sA + node * KP128 + q * 4;
            d[0] = f2tf(v.x); d[1] = f2tf(v.y); d[2] = f2tf(v.z); d[3] = f2tf(v.w);
        }
        __syncthreads();

        // GEMM1: h0 = x @ Wf^T  (2 n-tiles per warp)
        {
            int cb = cw * 16;
            float4 acc[2] = {};
#pragma unroll 4
            for (int ks = 0; ks < 16; ks++) {
                int ko = ks * 8;
                uint32_t a0 = sA[(r0 + g) * KP128 + ko + tig];
                uint32_t a1 = sA[(r0 + g + 8) * KP128 + ko + tig];
                uint32_t a2 = sA[(r0 + g) * KP128 + ko + tig + 4];
                uint32_t a3 = sA[(r0 + g + 8) * KP128 + ko + tig + 4];
#pragma unroll
                for (int nt = 0; nt < 2; nt++) {
                    int o = cb + nt * 8 + g;
                    mma8(acc[nt], a0, a1, a2, a3,
                         sWf[o * KP128 + ko + tig], sWf[o * KP128 + ko + tig + 4]);
                }
            }
#pragma unroll
            for (int nt = 0; nt < 2; nt++) {
                int c = cb + nt * 8 + tig * 2;
                int n1 = base + r0 + g, n2 = n1 + 8;
                float v0 = acc[nt].x + sbf[c], v1 = acc[nt].y + sbf[c + 1];
                float v2 = acc[nt].z + sbf[c], v3 = acc[nt].w + sbf[c + 1];
                if (n1 < NN)
                    *(__half2*)(g_h0h + n1 * HH + c) = __floats2half2_rn(v0, v1);
                if (n2 < NN)
                    *(__half2*)(g_h0h + n2 * HH + c) = __floats2half2_rn(v2, v3);
                sG[(r0 + g) * KP64 + c]         = f2tf(v0);
                sG[(r0 + g) * KP64 + c + 1]     = f2tf(v1);
                sG[(r0 + g + 8) * KP64 + c]     = f2tf(v2);
                sG[(r0 + g + 8) * KP64 + c + 1] = f2tf(v3);
            }
        }
        __syncthreads();

        // GEMM2: ghh = h0 @ Whh^T  (6 n-tiles per warp)
        {
            int cb = cw * 48;
            float4 acc[6] = {};
            for (int ks = 0; ks < 8; ks++) {
                int ko = ks * 8;
                uint32_t a0 = sG[(r0 + g) * KP64 + ko + tig];
                uint32_t a1 = sG[(r0 + g + 8) * KP64 + ko + tig];
                uint32_t a2 = sG[(r0 + g) * KP64 + ko + tig + 4];
                uint32_t a3 = sG[(r0 + g + 8) * KP64 + ko + tig + 4];
#pragma unroll
                for (int nt = 0; nt < 6; nt++) {
                    int o = cb + nt * 8 + g;
                    mma8(acc[nt], a0, a1, a2, a3,
                         sWhh[o * KP64 + ko + tig], sWhh[o * KP64 + ko + tig + 4]);
                }
            }
#pragma unroll
            for (int nt = 0; nt < 6; nt++) {
                int c = cb + nt * 8 + tig * 2;
                int n1 = base + r0 + g, n2 = n1 + 8;
                if (n1 < NN)
                    *(__half2*)(g_ghhh + n1 * 192 + c) =
                        __floats2half2_rn(acc[nt].x + sbhh[c], acc[nt].y + sbhh[c + 1]);
                if (n2 < NN)
                    *(__half2*)(g_ghhh + n2 * 192 + c) =
                        __floats2half2_rn(acc[nt].z + sbhh[c], acc[nt].w + sbhh[c + 1]);
            }
        }
        __syncthreads();
    }
}

// ---------------- edge propagation: 16 lanes/edge, LDG.64 gather, RED.v4 ----
__global__ __launch_bounds__(256) void k_prop(int use_mid,
                                              const int* __restrict__ ei1,
                                              const float* __restrict__ ew1,
                                              const int* __restrict__ ei2,
                                              const float* __restrict__ ew2) {
    const __half* xin = use_mid ? g_xmidh : g_h0h;
    int group = blockIdx.x * 16 + (threadIdx.x >> 4);
    int l16 = threadIdx.x & 15;
    int slot0 = group * 2;   // even; pair never straddles EE

    const int* ei;
    const float* ew;
    float* out;
    int e0;
    if (slot0 < EE) { e0 = slot0;      ei = ei1; ew = ew1; out = g_x1; }
    else            { e0 = slot0 - EE; ei = ei2; ew = ew2; out = g_x2; }

    int2   sp = *(const int2*)(ei + e0);        // src pair
    int2   dp = *(const int2*)(ei + EE + e0);   // dst pair
    float2 wp = *(const float2*)(ew + e0);      // weight pair

    // one LDG.64 per lane: 4 halves = 8 bytes (aligned: l16*4 halves = 8B)
    uint2 ua = *(const uint2*)(xin + sp.x * HH + l16 * 4);
    uint2 ub = *(const uint2*)(xin + sp.y * HH + l16 * 4);

    float2 f0 = __half22float2(*(__half2*)&ua.x);
    float2 f1 = __half22float2(*(__half2*)&ua.y);
    float2 g0 = __half22float2(*(__half2*)&ub.x);
    float2 g1 = __half22float2(*(__half2*)&ub.y);

    float* q0 = out + dp.x * HH + l16 * 4;
    float* q1 = out + dp.y * HH + l16 * 4;
    asm volatile("red.global.add.v4.f32 [%0], {%1, %2, %3, %4};"
                 :: "l"(q0), "f"(f0.x * wp.x), "f"(f0.y * wp.x),
                    "f"(f1.x * wp.x), "f"(f1.y * wp.x) : "memory");
    asm volatile("red.global.add.v4.f32 [%0], {%1, %2, %3, %4};"
                 :: "l"(q1), "f"(g0.x * wp.y), "f"(g0.y * wp.y),
                    "f"(g1.x * wp.y), "f"(g1.y * wp.y) : "memory");
}

// ---------------- persistent fused concat-linear + GRU + out ----------------
#define O_A    0
#define O_WC   (O_A + 128 * KP128)
#define O_WIH  (O_WC + 64 * KP128)
#define O_WL   (O_WIH + 192 * KP64)
#define O_G    (O_WL + 64 * KP64)
#define O_BC   (O_G + 128 * KP64)
#define O_BIH  (O_BC + 64)
#define O_BL   (O_BIH + 192)
#define O_LY   (O_BL + 64)
#define CG_WORDS (O_LY + 128 * 17)

template <bool FINAL>
__global__ __launch_bounds__(1024, 1) void k_congru(
    const float* __restrict__ Wc,  const float* __restrict__ bc,
    const float* __restrict__ Wih, const float* __restrict__ bih,
    const float* __restrict__ Wl,  const float* __restrict__ bl,
    float* __restrict__ dout) {
    extern __shared__ uint32_t sm[];
    uint32_t* sA   = sm + O_A;
    uint32_t* sWc  = sm + O_WC;
    uint32_t* sWih = sm + O_WIH;
    uint32_t* sWl  = sm + O_WL;
    uint32_t* sG   = sm + O_G;
    float* sbc  = (float*)(sm + O_BC);
    float* sbih = (float*)(sm + O_BIH);
    float* sbl  = (float*)(sm + O_BL);
    float* sLY  = (float*)(sm + O_LY);
    const int OC = FINAL ? CC : HH;

    int t = threadIdx.x;

    // stage weights ONCE
    for (int i = t; i < 64 * 32; i += 1024) {
        int o = i >> 5, q = i & 31;
        float4 v = *(const float4*)(Wc + o * FF + q * 4);
        uint32_t* d = sWc + o * KP128 + q * 4;
        d[0] = f2tf(v.x); d[1] = f2tf(v.y); d[2] = f2tf(v.z); d[3] = f2tf(v.w);
    }
    for (int i = t; i < 192 * 16; i += 1024) {
        int o = i >> 4, q = i & 15;
        float4 v = *(const float4*)(Wih + o * HH + q * 4);
        uint32_t* d = sWih + o * KP64 + q * 4;
        d[0] = f2tf(v.x); d[1] = f2tf(v.y); d[2] = f2tf(v.z); d[3] = f2tf(v.w);
    }
    for (int i = t; i < OC * 16; i += 1024) {
        int o = i >> 4, q = i & 15;
        float4 v = *(const float4*)(Wl + o * HH + q * 4);
        uint32_t* d = sWl + o * KP64 + q * 4;
        d[0] = f2tf(v.x); d[1] = f2tf(v.y); d[2] = f2tf(v.z); d[3] = f2tf(v.w);
    }
    if (t < 64)  sbc[t]  = bc[t];
    if (t < 192) sbih[t] = bih[t];
    if (t < OC)  sbl[t]  = bl[t];
    __syncthreads();

    int w = t >> 5, lane = t & 31, g = lane >> 2, tig = lane & 3;
    int r0 = (w & 7) * 16, cw = w >> 3, cb = cw * 16;

    for (int tile = blockIdx.x; tile < NB; tile += gridDim.x) {
        int base = tile * 128;
        for (int i = t; i < 128 * 16; i += 1024) {
            int node = i >> 4, q = i & 15;
            int n = base + node;
            float4 v1 = make_float4(0.f, 0.f, 0.f, 0.f), v2 = v1;
            if (n < NN) {
                v1 = *(const float4*)(g_x1 + n * HH + q * 4);
                v2 = *(const float4*)(g_x2 + n * HH + q * 4);
            }
            uint32_t* d1 = sA + node * KP128 + q * 4;
            uint32_t* dd2 = d1 + 64;
            d1[0] = f2tf(v1.x); d1[1] = f2tf(v1.y); d1[2] = f2tf(v1.z); d1[3] = f2tf(v1.w);
            dd2[0] = f2tf(v2.x); dd2[1] = f2tf(v2.y); dd2[2] = f2tf(v2.z); dd2[3] = f2tf(v2.w);
        }
        __syncthreads();

        // phase 1: gg = [x1|x2] @ Wc^T + bc  (2 n-tiles per warp)
        {
            float4 acc[2] = {};
#pragma unroll 4
            for (int ks = 0; ks < 16; ks++) {
                int ko = ks * 8;
                uint32_t a0 = sA[(r0 + g) * KP128 + ko + tig];
                uint32_t a1 = sA[(r0 + g + 8) * KP128 + ko + tig];
                uint32_t a2 = sA[(r0 + g) * KP128 + ko + tig + 4];
                uint32_t a3 = sA[(r0 + g + 8) * KP128 + ko + tig + 4];
#pragma unroll
                for (int nt = 0; nt < 2; nt++) {
                    int o = cb + nt * 8 + g;
                    mma8(acc[nt], a0, a1, a2, a3,
                         sWc[o * KP128 + ko + tig], sWc[o * KP128 + ko + tig + 4]);
                }
            }
#pragma unroll
            for (int nt = 0; nt < 2; nt++) {
                int c = cb + nt * 8 + tig * 2;
                sG[(r0 + g) * KP64 + c]         = f2tf(acc[nt].x + sbc[c]);
                sG[(r0 + g) * KP64 + c + 1]     = f2tf(acc[nt].y + sbc[c + 1]);
                sG[(r0 + g + 8) * KP64 + c]     = f2tf(acc[nt].z + sbc[c]);
                sG[(r0 + g + 8) * KP64 + c + 1] = f2tf(acc[nt].w + sbc[c + 1]);
            }
        }
        __syncthreads();

        // phase 2: gi = gg @ Wih^T  (3 gates x 2 n-tiles per warp)
        float4 d2[3][2];
#pragma unroll
        for (int gt = 0; gt < 3; gt++)
#pragma unroll
            for (int nt = 0; nt < 2; nt++)
                d2[gt][nt] = make_float4(0.f, 0.f, 0.f, 0.f);
        for (int ks = 0; ks < 8; ks++) {
            int ko = ks * 8;
            uint32_t a0 = sG[(r0 + g) * KP64 + ko + tig];
            uint32_t a1 = sG[(r0 + g + 8) * KP64 + ko + tig];
            uint32_t a2 = sG[(r0 + g) * KP64 + ko + tig + 4];
            uint32_t a3 = sG[(r0 + g + 8) * KP64 + ko + tig + 4];
#pragma unroll
            for (int gt = 0; gt < 3; gt++)
#pragma unroll
                for (int nt = 0; nt < 2; nt++) {
                    int o = gt * 64 + cb + nt * 8 + g;
                    mma8(d2[gt][nt], a0, a1, a2, a3,
                         sWih[o * KP64 + ko + tig], sWih[o * KP64 + ko + tig + 4]);
                }
        }

        // phase 3: GRU elementwise (ghh, h both fp16)
        float hn[2][4];
#pragma unroll
        for (int nt = 0; nt < 2; nt++) {
            int c = cb + nt * 8 + tig * 2;
#pragma unroll
            for (int half = 0; half < 2; half++) {
                int node = base + r0 + g + half * 8;
                float vr0 = half ? d2[0][nt].z : d2[0][nt].x;
                float vr1 = half ? d2[0][nt].w : d2[0][nt].y;
                float vz0 = half ? d2[1][nt].z : d2[1][nt].x;
                float vz1 = half ? d2[1][nt].w : d2[1][nt].y;
                float vn0 = half ? d2[2][nt].z : d2[2][nt].x;
                float vn1 = half ? d2[2][nt].w : d2[2][nt].y;
                float o0 = 0.f, o1 = 0.f;
                if (node < NN) {
                    float2 gr = __half22float2(*(const __half2*)(g_ghhh + node * 192 + c));
                    float2 gz = __half22float2(*(const __half2*)(g_ghhh + node * 192 + 64 + c));
                    float2 gn = __half22float2(*(const __half2*)(g_ghhh + node * 192 + 128 + c));
                    float2 h  = __half22float2(*(const __half2*)(g_h0h + node * HH + c));
                    float r = sigf(vr0 + sbih[c] + gr.x);
                    float z = sigf(vz0 + sbih[64 + c] + gz.x);
                    float n = tanhf(vn0 + sbih[128 + c] + r * gn.x);
                    o0 = (1.f - z) * n + z * h.x;
                    r = sigf(vr1 + sbih[c + 1] + gr.y);
                    z = sigf(vz1 + sbih[64 + c + 1] + gz.y);
                    n = tanhf(vn1 + sbih[128 + c + 1] + r * gn.y);
                    o1 = (1.f - z) * n + z * h.y;
                }
                hn[nt][half * 2] = o0;
                hn[nt][half * 2 + 1] = o1;
            }
        }
        __syncthreads();
#pragma unroll
        for (int nt = 0; nt < 2; nt++) {
            int c = cb + nt * 8 + tig * 2;
            sG[(r0 + g) * KP64 + c]         = f2tf(hn[nt][0]);
            sG[(r0 + g) * KP64 + c + 1]     = f2tf(hn[nt][1]);
            sG[(r0 + g + 8) * KP64 + c]     = f2tf(hn[nt][2]);
            sG[(r0 + g + 8) * KP64 + c + 1] = f2tf(hn[nt][3]);
        }
        __syncthreads();

        // phase 4: output GEMM
        if (!FINAL) {
            float4 acc[2] = {};
            for (int ks = 0; ks < 8; ks++) {
                int ko = ks * 8;
                uint32_t a0 = sG[(r0 + g) * KP64 + ko + tig];
                uint32_t a1 = sG[(r0 + g + 8) * KP64 + ko + tig];
                uint32_t a2 = sG[(r0 + g) * KP64 + ko + tig + 4];
                uint32_t a3 = sG[(r0 + g + 8) * KP64 + ko + tig + 4];
#pragma unroll
                for (int nt = 0; nt < 2; nt++) {
                    int o = cb + nt * 8 + g;
                    mma8(acc[nt], a0, a1, a2, a3,
                         sWl[o * KP64 + ko + tig], sWl[o * KP64 + ko + tig + 4]);
                }
            }
#pragma unroll
            for (int nt = 0; nt < 2; nt++) {
                int c = cb + nt * 8 + tig * 2;
                int n1 = base + r0 + g, n2 = n1 + 8;
                if (n1 < NN)
                    *(__half2*)(g_xmidh + n1 * HH + c) =
                        __floats2half2_rn(acc[nt].x + sbl[c], acc[nt].y + sbl[c + 1]);
                if (n2 < NN)
                    *(__half2*)(g_xmidh + n2 * HH + c) =
                        __floats2half2_rn(acc[nt].z + sbl[c], acc[nt].w + sbl[c + 1]);
            }
        } else {
            if (cw < 2) {
                float4 acc = make_float4(0.f, 0.f, 0.f, 0.f);
                int c0f = cw * 8;
                for (int ks = 0; ks < 8; ks++) {
                    int ko = ks * 8;
                    uint32_t a0 = sG[(r0 + g) * KP64 + ko + tig];
                    uint32_t a1 = sG[(r0 + g + 8) * KP64 + ko + tig];
                    uint32_t a2 = sG[(r0 + g) * KP64 + ko + tig + 4];
                    uint32_t a3 = sG[(r0 + g + 8) * KP64 + ko + tig + 4];
                    int o = c0f + g;
                    mma8(acc, a0, a1, a2, a3,
                         sWl[o * KP64 + ko + tig], sWl[o * KP64 + ko + tig + 4]);
                }
                int c = c0f + tig * 2;
                sLY[(r0 + g) * 17 + c]         = acc.x + sbl[c];
                sLY[(r0 + g) * 17 + c + 1]     = acc.y + sbl[c + 1];
                sLY[(r0 + g + 8) * 17 + c]     = acc.z + sbl[c];
                sLY[(r0 + g + 8) * 17 + c + 1] = acc.w + sbl[c + 1];
            }
            __syncthreads();
            if (t < 128) {
                int node = base + t;
                if (node < NN) {
                    float m = -1e30f;
#pragma unroll
                    for (int cc = 0; cc < 16; cc++) m = fmaxf(m, sLY[t * 17 + cc]);
                    float s = 0.f;
#pragma unroll
                    for (int cc = 0; cc < 16; cc++) s += expf(sLY[t * 17 + cc] - m);
                    float l = m + logf(s);
#pragma unroll
                    for (int cc = 0; cc < 16; cc++)
                        dout[node * CC + cc] = sLY[t * 17 + cc] - l;
                }
            }
        }
        __syncthreads();
    }
}

// ---------------- launch -----------------------------------------------------
extern "C" void kernel_launch(void* const* d_in, const int* in_sizes, int n_in,
                              void* d_out, int out_size) {
    const float* x       = (const float*)d_in[0];
    const int*   ei      = (const int*)  d_in[1];
    const float* ew      = (const float*)d_in[2];
    const int*   eir     = (const int*)  d_in[3];
    const float* ewr     = (const float*)d_in[4];
    const float* W_first = (const float*)d_in[5];
    const float* b_first = (const float*)d_in[6];
    const float* W_con1  = (const float*)d_in[7];
    const float* b_con1  = (const float*)d_in[8];
    const float* W_con2  = (const float*)d_in[9];
    const float* b_con2  = (const float*)d_in[10];
    const float* W_lin1  = (const float*)d_in[11];
    const float* b_lin1  = (const float*)d_in[12];
    const float* W_out   = (const float*)d_in[13];
    const float* b_out   = (const float*)d_in[14];
    const float* W_ih    = (const float*)d_in[15];
    const float* W_hh    = (const float*)d_in[16];
    const float* b_ih    = (const float*)d_in[17];
    const float* b_hh    = (const float*)d_in[18];
    float* out = (float*)d_out;

    const int SM_FG = FG_WORDS * 4;
    const int SM_CG = CG_WORDS * 4;

    cudaFuncSetAttribute(k_fg, cudaFuncAttributeMaxDynamicSharedMemorySize, SM_FG);
    cudaFuncSetAttribute(k_congru<false>,
                         cudaFuncAttributeMaxDynamicSharedMemorySize, SM_CG);
    cudaFuncSetAttribute(k_congru<true>,
                         cudaFuncAttributeMaxDynamicSharedMemorySize, SM_CG);

    const int PERS = 148;                     // persistent: 1 CTA per SM
    const int PROP_BLOCKS = (2 * EE) / 32;    // 2 edges per 16-lane group

    k_zero<<<1024, 256>>>();
    k_fg<<<PERS, 1024, SM_FG>>>(x, W_first, b_first, W_hh, b_hh);
    k_prop<<<PROP_BLOCKS, 256>>>(0, ei, ew, eir, ewr);
    k_congru<false><<<PERS, 1024, SM_CG>>>(W_con1, b_con1, W_ih, b_ih,
                                           W_lin1, b_lin1, nullptr);
    k_zero<<<1024, 256>>>();
    k_prop<<<PROP_BLOCKS, 256>>>(1, ei, ew, eir, ewr);
    k_congru<true><<<PERS, 1024, SM_CG>>>(W_con2, b_con2, W_ih, b_ih,
                                          W_out, b_out, out);
}

// round 10
// speedup vs baseline: 1.6727x; 1.2753x over previous
#include <cuda_runtime.h>
#include <cuda_fp16.h>
#include <math.h>
#include <stdint.h>

#define NN 100000
#define FF 128
#define HH 64
#define CC 16
#define EE 1000000
#define NB 782   // ceil(NN/128)

// word strides (uint32 units), all ≡ 4 (mod 32) for conflict-free lane maps
#define WP128 68   // K=128 fp16 operand row (128 halves + pad)
#define WP64  36   // K=64 fp16 operand row
#define WGH  100   // ghh prefetch row (192 halves + pad)
#define WH0   36   // h0 prefetch row (64 halves + pad)

// ---------------- scratch ----------------------------------------------------
__device__ __align__(16) __half g_h0h[NN * HH];
__device__ __align__(16) __half g_xmidh[NN * HH];
__device__ __align__(16) __half g_ghhh[NN * 192];
__device__ __align__(16) float  g_x1[NN * HH];
__device__ __align__(16) float  g_x2[NN * HH];

// ---------------- helpers -----------------------------------------------------
__device__ __forceinline__ uint32_t f2h2(float a, float b) {
    __half2 h = __floats2half2_rn(a, b);
    return *(uint32_t*)&h;
}
__device__ __forceinline__ float2 h2f2(uint32_t u) {
    return __half22float2(*(__half2*)&u);
}
__device__ __forceinline__ void mma16(float4& d, uint32_t a0, uint32_t a1,
                                      uint32_t a2, uint32_t a3,
                                      uint32_t b0, uint32_t b1) {
    asm volatile(
        "mma.sync.aligned.m16n8k16.row.col.f32.f16.f16.f32 "
        "{%0,%1,%2,%3},{%4,%5,%6,%7},{%8,%9},{%0,%1,%2,%3};"
        : "+f"(d.x), "+f"(d.y), "+f"(d.z), "+f"(d.w)
        : "r"(a0), "r"(a1), "r"(a2), "r"(a3), "r"(b0), "r"(b1));
}
__device__ __forceinline__ float sigf(float x) {
    return 1.f / (1.f + __expf(-x));
}
__device__ __forceinline__ uint32_t smem_u32(const void* p) {
    uint32_t a;
    asm("{ .reg .u64 t; cvta.to.shared.u64 t, %1; cvt.u32.u64 %0, t; }"
        : "=r"(a) : "l"(p));
    return a;
}
#define CP_ASYNC16(dst, src) \
    asm volatile("cp.async.cg.shared.global [%0], [%1], 16;" \
                 :: "r"(dst), "l"(src) : "memory")
#define CP_COMMIT() asm volatile("cp.async.commit_group;" ::: "memory")
#define CP_WAIT0()  asm volatile("cp.async.wait_group 0;" ::: "memory")

// ---------------- zero the two scatter buffers -------------------------------
__global__ void k_zero() {
    const int tot = NN * HH / 4;
    float4 z = make_float4(0.f, 0.f, 0.f, 0.f);
    for (int i = blockIdx.x * blockDim.x + threadIdx.x; i < tot;
         i += gridDim.x * blockDim.x) {
        reinterpret_cast<float4*>(g_x1)[i] = z;
        reinterpret_cast<float4*>(g_x2)[i] = z;
    }
}

// ---------------- persistent k_fg: h0 = x@Wf^T+bf ; ghh = h0@Whh^T+bhh -------
#define FG_A    0                          // 128 x WP128
#define FG_WF   (FG_A + 128 * WP128)       // 64 x WP128
#define FG_WHH  (FG_WF + 64 * WP128)       // 192 x WP64
#define FG_G    (FG_WHH + 192 * WP64)      // 128 x WP64 (h0, fp16)
#define FG_WORDS (FG_G + 128 * WP64)

__global__ __launch_bounds__(1024, 1) void k_fg(const float* __restrict__ x,
                                                const float* __restrict__ Wf,
                                                const float* __restrict__ bf,
                                                const float* __restrict__ Whh,
                                                const float* __restrict__ bhh) {
    extern __shared__ uint32_t sm[];
    uint32_t* sA   = sm + FG_A;
    uint32_t* sWf  = sm + FG_WF;
    uint32_t* sWhh = sm + FG_WHH;
    uint32_t* sG   = sm + FG_G;
    __shared__ float sbf[64];
    __shared__ float sbhh[192];
    int t = threadIdx.x;

    // stage weights ONCE (fp16)
    for (int i = t; i < 64 * 32; i += 1024) {
        int o = i >> 5, q = i & 31;
        float4 v = *(const float4*)(Wf + o * FF + q * 4);
        sWf[o * WP128 + q * 2]     = f2h2(v.x, v.y);
        sWf[o * WP128 + q * 2 + 1] = f2h2(v.z, v.w);
    }
    for (int i = t; i < 192 * 16; i += 1024) {
        int o = i >> 4, q = i & 15;
        float4 v = *(const float4*)(Whh + o * HH + q * 4);
        sWhh[o * WP64 + q * 2]     = f2h2(v.x, v.y);
        sWhh[o * WP64 + q * 2 + 1] = f2h2(v.z, v.w);
    }
    if (t < 64) sbf[t] = bf[t];
    if (t >= 256 && t < 448) sbhh[t - 256] = bhh[t - 256];
    __syncthreads();

    int w = t >> 5, lane = t & 31, g = lane >> 2, tig = lane & 3;
    int r0 = (w & 7) * 16, cw = w >> 3;

    for (int tile = blockIdx.x; tile < NB; tile += gridDim.x) {
        int base = tile * 128;
        for (int i = t; i < 128 * 32; i += 1024) {
            int node = i >> 5, q = i & 31;
            float4 v = make_float4(0.f, 0.f, 0.f, 0.f);
            if (base + node < NN)
                v = *(const float4*)(x + (base + node) * FF + q * 4);
            sA[node * WP128 + q * 2]     = f2h2(v.x, v.y);
            sA[node * WP128 + q * 2 + 1] = f2h2(v.z, v.w);
        }
        __syncthreads();

        // GEMM1: h0 = x @ Wf^T  (K=128, 8 k16 steps, 2 n-tiles/warp)
        {
            int cb = cw * 16;
            float4 acc[2] = {};
#pragma unroll
            for (int s = 0; s < 8; s++) {
                int ko = s * 8;
                uint32_t a0 = sA[(r0 + g) * WP128 + ko + tig];
                uint32_t a1 = sA[(r0 + g + 8) * WP128 + ko + tig];
                uint32_t a2 = sA[(r0 + g) * WP128 + ko + tig + 4];
                uint32_t a3 = sA[(r0 + g + 8) * WP128 + ko + tig + 4];
#pragma unroll
                for (int nt = 0; nt < 2; nt++) {
                    int o = cb + nt * 8 + g;
                    mma16(acc[nt], a0, a1, a2, a3,
                          sWf[o * WP128 + ko + tig], sWf[o * WP128 + ko + tig + 4]);
                }
            }
#pragma unroll
            for (int nt = 0; nt < 2; nt++) {
                int c = cb + nt * 8 + tig * 2;
                int n1 = base + r0 + g, n2 = n1 + 8;
                float v0 = acc[nt].x + sbf[c], v1 = acc[nt].y + sbf[c + 1];
                float v2 = acc[nt].z + sbf[c], v3 = acc[nt].w + sbf[c + 1];
                uint32_t p01 = f2h2(v0, v1), p23 = f2h2(v2, v3);
                if (n1 < NN) *(uint32_t*)(g_h0h + n1 * HH + c) = p01;
                if (n2 < NN) *(uint32_t*)(g_h0h + n2 * HH + c) = p23;
                int cwd = (c >> 1);
                sG[(r0 + g) * WP64 + cwd]     = p01;
                sG[(r0 + g + 8) * WP64 + cwd] = p23;
            }
        }
        __syncthreads();

        // GEMM2: ghh = h0 @ Whh^T  (K=64, 4 k16 steps, 6 n-tiles/warp)
        {
            int cb = cw * 48;
            float4 acc[6] = {};
#pragma unroll
            for (int s = 0; s < 4; s++) {
                int ko = s * 8;
                uint32_t a0 = sG[(r0 + g) * WP64 + ko + tig];
                uint32_t a1 = sG[(r0 + g + 8) * WP64 + ko + tig];
                uint32_t a2 = sG[(r0 + g) * WP64 + ko + tig + 4];
                uint32_t a3 = sG[(r0 + g + 8) * WP64 + ko + tig + 4];
#pragma unroll
                for (int nt = 0; nt < 6; nt++) {
                    int o = cb + nt * 8 + g;
                    mma16(acc[nt], a0, a1, a2, a3,
                          sWhh[o * WP64 + ko + tig], sWhh[o * WP64 + ko + tig + 4]);
                }
            }
#pragma unroll
            for (int nt = 0; nt < 6; nt++) {
                int c = cb + nt * 8 + tig * 2;
                int n1 = base + r0 + g, n2 = n1 + 8;
                if (n1 < NN)
                    *(uint32_t*)(g_ghhh + n1 * 192 + c) =
                        f2h2(acc[nt].x + sbhh[c], acc[nt].y + sbhh[c + 1]);
                if (n2 < NN)
                    *(uint32_t*)(g_ghhh + n2 * 192 + c) =
                        f2h2(acc[nt].z + sbhh[c], acc[nt].w + sbhh[c + 1]);
            }
        }
        __syncthreads();
    }
}

// ---------------- edge propagation: 16 lanes/edge, contiguous RED.v4 (R6) ----
__global__ __launch_bounds__(256) void k_prop(int use_mid,
                                              const int* __restrict__ ei1,
                                              const float* __restrict__ ew1,
                                              const int* __restrict__ ei2,
                                              const float* __restrict__ ew2) {
    const __half* xin = use_mid ? g_xmidh : g_h0h;
    int group = blockIdx.x * 16 + (threadIdx.x >> 4);
    int l16 = threadIdx.x & 15;
    int slot0 = group * 2;   // even; pair never straddles EE

    const int* ei;
    const float* ew;
    float* out;
    int e0;
    if (slot0 < EE) { e0 = slot0;      ei = ei1; ew = ew1; out = g_x1; }
    else            { e0 = slot0 - EE; ei = ei2; ew = ew2; out = g_x2; }

    int s0 = __ldg(ei + e0),      s1 = __ldg(ei + e0 + 1);
    int d0 = __ldg(ei + EE + e0), d1 = __ldg(ei + EE + e0 + 1);
    float w0 = __ldg(ew + e0),    w1 = __ldg(ew + e0 + 1);

    const __half2* p0 = (const __half2*)(xin + s0 * HH + l16 * 4);
    const __half2* p1 = (const __half2*)(xin + s1 * HH + l16 * 4);
    __half2 a0 = p0[0], a1 = p0[1];
    __half2 b0 = p1[0], b1 = p1[1];

    float2 f0 = __half22float2(a0), f1 = __half22float2(a1);
    float2 g0 = __half22float2(b0), g1 = __half22float2(b1);

    float* q0 = out + d0 * HH + l16 * 4;
    float* q1 = out + d1 * HH + l16 * 4;
    asm volatile("red.global.add.v4.f32 [%0], {%1, %2, %3, %4};"
                 :: "l"(q0), "f"(f0.x * w0), "f"(f0.y * w0),
                    "f"(f1.x * w0), "f"(f1.y * w0) : "memory");
    asm volatile("red.global.add.v4.f32 [%0], {%1, %2, %3, %4};"
                 :: "l"(q1), "f"(g0.x * w1), "f"(g0.y * w1),
                    "f"(g1.x * w1), "f"(g1.y * w1) : "memory");
}

// ---------------- persistent fused concat-linear + GRU + out ----------------
#define O_A    0                           // 128 x WP128 (concat, fp16)
#define O_WC   (O_A + 128 * WP128)         // 64 x WP128
#define O_WIH  (O_WC + 64 * WP128)         // 192 x WP64
#define O_WL   (O_WIH + 192 * WP64)        // 64 x WP64
#define O_G    (O_WL + 64 * WP64)          // 128 x WP64 (gg / hnew, fp16)
#define O_GH   (O_G + 128 * WP64)          // 128 x WGH  (ghh prefetch)
#define O_H0   (O_GH + 128 * WGH)          // 128 x WH0  (h0 prefetch)
#define O_BC   (O_H0 + 128 * WH0)
#define O_BIH  (O_BC + 64)
#define O_BL   (O_BIH + 192)
#define O_LY   (O_BL + 64)
#define CG_WORDS (O_LY + 128 * 17)

template <bool FINAL>
__global__ __launch_bounds__(1024, 1) void k_congru(
    const float* __restrict__ Wc,  const float* __restrict__ bc,
    const float* __restrict__ Wih, const float* __restrict__ bih,
    const float* __restrict__ Wl,  const float* __restrict__ bl,
    float* __restrict__ dout) {
    extern __shared__ uint32_t sm[];
    uint32_t* sA   = sm + O_A;
    uint32_t* sWc  = sm + O_WC;
    uint32_t* sWih = sm + O_WIH;
    uint32_t* sWl  = sm + O_WL;
    uint32_t* sG   = sm + O_G;
    uint32_t* sGH  = sm + O_GH;
    uint32_t* sH0  = sm + O_H0;
    float* sbc  = (float*)(sm + O_BC);
    float* sbih = (float*)(sm + O_BIH);
    float* sbl  = (float*)(sm + O_BL);
    float* sLY  = (float*)(sm + O_LY);
    const int OC = FINAL ? CC : HH;

    int t = threadIdx.x;
    uint32_t sGH_b = smem_u32(sGH);
    uint32_t sH0_b = smem_u32(sH0);

    // stage weights ONCE (fp16)
    for (int i = t; i < 64 * 32; i += 1024) {
        int o = i >> 5, q = i & 31;
        float4 v = *(const float4*)(Wc + o * FF + q * 4);
        sWc[o * WP128 + q * 2]     = f2h2(v.x, v.y);
        sWc[o * WP128 + q * 2 + 1] = f2h2(v.z, v.w);
    }
    for (int i = t; i < 192 * 16; i += 1024) {
        int o = i >> 4, q = i & 15;
        float4 v = *(const float4*)(Wih + o * HH + q * 4);
        sWih[o * WP64 + q * 2]     = f2h2(v.x, v.y);
        sWih[o * WP64 + q * 2 + 1] = f2h2(v.z, v.w);
    }
    for (int i = t; i < OC * 16; i += 1024) {
        int o = i >> 4, q = i & 15;
        float4 v = *(const float4*)(Wl + o * HH + q * 4);
        sWl[o * WP64 + q * 2]     = f2h2(v.x, v.y);
        sWl[o * WP64 + q * 2 + 1] = f2h2(v.z, v.w);
    }
    if (t < 64)  sbc[t]  = bc[t];
    if (t < 192) sbih[t] = bih[t];
    if (t < OC)  sbl[t]  = bl[t];
    __syncthreads();

    int w = t >> 5, lane = t & 31, g = lane >> 2, tig = lane & 3;
    int r0 = (w & 7) * 16, cw = w >> 3, cb = cw * 16;

    for (int tile = blockIdx.x; tile < NB; tile += gridDim.x) {
        int base = tile * 128;
        // stage concat input (fp16) + launch ghh/h0 prefetch
        for (int i = t; i < 128 * 16; i += 1024) {
            int node = i >> 4, q = i & 15;
            int n = base + node;
            float4 v1 = make_float4(0.f, 0.f, 0.f, 0.f), v2 = v1;
            if (n < NN) {
                v1 = *(const float4*)(g_x1 + n * HH + q * 4);
                v2 = *(const float4*)(g_x2 + n * HH + q * 4);
            }
            sA[node * WP128 + q * 2]          = f2h2(v1.x, v1.y);
            sA[node * WP128 + q * 2 + 1]      = f2h2(v1.z, v1.w);
            sA[node * WP128 + 32 + q * 2]     = f2h2(v2.x, v2.y);
            sA[node * WP128 + 32 + q * 2 + 1] = f2h2(v2.z, v2.w);
        }
        // ghh: 128 rows x 24 chunks of 16B
        for (int i = t; i < 128 * 24; i += 1024) {
            int row = i / 24, ch = i % 24;
            int n = base + row;
            if (n < NN)
                CP_ASYNC16(sGH_b + (row * WGH + ch * 4) * 4,
                           (const char*)(g_ghhh + n * 192) + ch * 16);
        }
        // h0: 128 rows x 8 chunks of 16B
        for (int i = t; i < 128 * 8; i += 1024) {
            int row = i >> 3, ch = i & 7;
            int n = base + row;
            if (n < NN)
                CP_ASYNC16(sH0_b + (row * WH0 + ch * 4) * 4,
                           (const char*)(g_h0h + n * HH) + ch * 16);
        }
        CP_COMMIT();
        __syncthreads();

        // phase 1: gg = [x1|x2] @ Wc^T + bc  (K=128, 8 k16 steps)
        {
            float4 acc[2] = {};
#pragma unroll
            for (int s = 0; s < 8; s++) {
                int ko = s * 8;
                uint32_t a0 = sA[(r0 + g) * WP128 + ko + tig];
                uint32_t a1 = sA[(r0 + g + 8) * WP128 + ko + tig];
                uint32_t a2 = sA[(r0 + g) * WP128 + ko + tig + 4];
                uint32_t a3 = sA[(r0 + g + 8) * WP128 + ko + tig + 4];
#pragma unroll
                for (int nt = 0; nt < 2; nt++) {
                    int o = cb + nt * 8 + g;
                    mma16(acc[nt], a0, a1, a2, a3,
                          sWc[o * WP128 + ko + tig], sWc[o * WP128 + ko + tig + 4]);
                }
            }
#pragma unroll
            for (int nt = 0; nt < 2; nt++) {
                int c = cb + nt * 8 + tig * 2;
                int cwd = c >> 1;
                sG[(r0 + g) * WP64 + cwd] =
                    f2h2(acc[nt].x + sbc[c], acc[nt].y + sbc[c + 1]);
                sG[(r0 + g + 8) * WP64 + cwd] =
                    f2h2(acc[nt].z + sbc[c], acc[nt].w + sbc[c + 1]);
            }
        }
        __syncthreads();

        // phase 2: gi = gg @ Wih^T  (K=64, 4 k16 steps, 3 gates x 2 nt)
        float4 d2[3][2];
#pragma unroll
        for (int gt = 0; gt < 3; gt++)
#pragma unroll
            for (int nt = 0; nt < 2; nt++)
                d2[gt][nt] = make_float4(0.f, 0.f, 0.f, 0.f);
#pragma unroll
        for (int s = 0; s < 4; s++) {
            int ko = s * 8;
            uint32_t a0 = sG[(r0 + g) * WP64 + ko + tig];
            uint32_t a1 = sG[(r0 + g + 8) * WP64 + ko + tig];
            uint32_t a2 = sG[(r0 + g) * WP64 + ko + tig + 4];
            uint32_t a3 = sG[(r0 + g + 8) * WP64 + ko + tig + 4];
#pragma unroll
            for (int gt = 0; gt < 3; gt++)
#pragma unroll
                for (int nt = 0; nt < 2; nt++) {
                    int o = gt * 64 + cb + nt * 8 + g;
                    mma16(d2[gt][nt], a0, a1, a2, a3,
                          sWih[o * WP64 + ko + tig], sWih[o * WP64 + ko + tig + 4]);
                }
        }

        // prefetched ghh/h0 now needed
        CP_WAIT0();
        __syncthreads();

        // phase 3: GRU elementwise (from prefetched smem)
        float hn[2][4];
#pragma unroll
        for (int nt = 0; nt < 2; nt++) {
            int c = cb + nt * 8 + tig * 2;
            int cwd = c >> 1;
#pragma unroll
            for (int half = 0; half < 2; half++) {
                int nl = r0 + g + half * 8;
                float vr0 = half ? d2[0][nt].z : d2[0][nt].x;
                float vr1 = half ? d2[0][nt].w : d2[0][nt].y;
                float vz0 = half ? d2[1][nt].z : d2[1][nt].x;
                float vz1 = half ? d2[1][nt].w : d2[1][nt].y;
                float vn0 = half ? d2[2][nt].z : d2[2][nt].x;
                float vn1 = half ? d2[2][nt].w : d2[2][nt].y;
                float2 gr = h2f2(sGH[nl * WGH + cwd]);
                float2 gz = h2f2(sGH[nl * WGH + 32 + cwd]);
                float2 gn = h2f2(sGH[nl * WGH + 64 + cwd]);
                float2 h  = h2f2(sH0[nl * WH0 + cwd]);
                float r = sigf(vr0 + sbih[c] + gr.x);
                float z = sigf(vz0 + sbih[64 + c] + gz.x);
                float n = tanhf(vn0 + sbih[128 + c] + r * gn.x);
                hn[nt][half * 2] = (1.f - z) * n + z * h.x;
                r = sigf(vr1 + sbih[c + 1] + gr.y);
                z = sigf(vz1 + sbih[64 + c + 1] + gz.y);
                n = tanhf(vn1 + sbih[128 + c + 1] + r * gn.y);
                hn[nt][half * 2 + 1] = (1.f - z) * n + z * h.y;
            }
        }
        __syncthreads();
#pragma unroll
        for (int nt = 0; nt < 2; nt++) {
            int c = cb + nt * 8 + tig * 2;
            int cwd = c >> 1;
            sG[(r0 + g) * WP64 + cwd]     = f2h2(hn[nt][0], hn[nt][1]);
            sG[(r0 + g + 8) * WP64 + cwd] = f2h2(hn[nt][2], hn[nt][3]);
        }
        __syncthreads();

        // phase 4: output GEMM (K=64, 4 k16 steps)
        if (!FINAL) {
            float4 acc[2] = {};
#pragma unroll
            for (int s = 0; s < 4; s++) {
                int ko = s * 8;
                uint32_t a0 = sG[(r0 + g) * WP64 + ko + tig];
                uint32_t a1 = sG[(r0 + g + 8) * WP64 + ko + tig];
                uint32_t a2 = sG[(r0 + g) * WP64 + ko + tig + 4];
                uint32_t a3 = sG[(r0 + g + 8) * WP64 + ko + tig + 4];
#pragma unroll
                for (int nt = 0; nt < 2; nt++) {
                    int o = cb + nt * 8 + g;
                    mma16(acc[nt], a0, a1, a2, a3,
                          sWl[o * WP64 + ko + tig], sWl[o * WP64 + ko + tig + 4]);
                }
            }
#pragma unroll
            for (int nt = 0; nt < 2; nt++) {
                int c = cb + nt * 8 + tig * 2;
                int n1 = base + r0 + g, n2 = n1 + 8;
                if (n1 < NN)
                    *(uint32_t*)(g_xmidh + n1 * HH + c) =
                        f2h2(acc[nt].x + sbl[c], acc[nt].y + sbl[c + 1]);
                if (n2 < NN)
                    *(uint32_t*)(g_xmidh + n2 * HH + c) =
                        f2h2(acc[nt].z + sbl[c], acc[nt].w + sbl[c + 1]);
            }
        } else {
            if (cw < 2) {
                float4 acc = make_float4(0.f, 0.f, 0.f, 0.f);
                int c0f = cw * 8;
#pragma unroll
                for (int s = 0; s < 4; s++) {
                    int ko = s * 8;
                    uint32_t a0 = sG[(r0 + g) * WP64 + ko + tig];
                    uint32_t a1 = sG[(r0 + g + 8) * WP64 + ko + tig];
                    uint32_t a2 = sG[(r0 + g) * WP64 + ko + tig + 4];
                    uint32_t a3 = sG[(r0 + g + 8) * WP64 + ko + tig + 4];
                    int o = c0f + g;
                    mma16(acc, a0, a1, a2, a3,
                          sWl[o * WP64 + ko + tig], sWl[o * WP64 + ko + tig + 4]);
                }
                int c = c0f + tig * 2;
                sLY[(r0 + g) * 17 + c]         = acc.x + sbl[c];
                sLY[(r0 + g) * 17 + c + 1]     = acc.y + sbl[c + 1];
                sLY[(r0 + g + 8) * 17 + c]     = acc.z + sbl[c];
                sLY[(r0 + g + 8) * 17 + c + 1] = acc.w + sbl[c + 1];
            }
            __syncthreads();
            if (t < 128) {
                int node = base + t;
                if (node < NN) {
                    float m = -1e30f;
#pragma unroll
                    for (int cc = 0; cc < 16; cc++) m = fmaxf(m, sLY[t * 17 + cc]);
                    float s = 0.f;
#pragma unroll
                    for (int cc = 0; cc < 16; cc++) s += expf(sLY[t * 17 + cc] - m);
                    float l = m + logf(s);
#pragma unroll
                    for (int cc = 0; cc < 16; cc++)
                        dout[node * CC + cc] = sLY[t * 17 + cc] - l;
                }
            }
        }
        __syncthreads();
    }
}

// ---------------- launch -----------------------------------------------------
extern "C" void kernel_launch(void* const* d_in, const int* in_sizes, int n_in,
                              void* d_out, int out_size) {
    const float* x       = (const float*)d_in[0];
    const int*   ei      = (const int*)  d_in[1];
    const float* ew      = (const float*)d_in[2];
    const int*   eir     = (const int*)  d_in[3];
    const float* ewr     = (const float*)d_in[4];
    const float* W_first = (const float*)d_in[5];
    const float* b_first = (const float*)d_in[6];
    const float* W_con1  = (const float*)d_in[7];
    const float* b_con1  = (const float*)d_in[8];
    const float* W_con2  = (const float*)d_in[9];
    const float* b_con2  = (const float*)d_in[10];
    const float* W_lin1  = (const float*)d_in[11];
    const float* b_lin1  = (const float*)d_in[12];
    const float* W_out   = (const float*)d_in[13];
    const float* b_out   = (const float*)d_in[14];
    const float* W_ih    = (const float*)d_in[15];
    const float* W_hh    = (const float*)d_in[16];
    const float* b_ih    = (const float*)d_in[17];
    const float* b_hh    = (const float*)d_in[18];
    float* out = (float*)d_out;

    const int SM_FG = FG_WORDS * 4;
    const int SM_CG = CG_WORDS * 4;

    cudaFuncSetAttribute(k_fg, cudaFuncAttributeMaxDynamicSharedMemorySize, SM_FG);
    cudaFuncSetAttribute(k_congru<false>,
                         cudaFuncAttributeMaxDynamicSharedMemorySize, SM_CG);
    cudaFuncSetAttribute(k_congru<true>,
                         cudaFuncAttributeMaxDynamicSharedMemorySize, SM_CG);

    const int PERS = 148;
    const int PROP_BLOCKS = (2 * EE) / 32;

    k_zero<<<1024, 256>>>();
    k_fg<<<PERS, 1024, SM_FG>>>(x, W_first, b_first, W_hh, b_hh);
    k_prop<<<PROP_BLOCKS, 256>>>(0, ei, ew, eir, ewr);
    k_congru<false><<<PERS, 1024, SM_CG>>>(W_con1, b_con1, W_ih, b_ih,
                                           W_lin1, b_lin1, nullptr);
    k_zero<<<1024, 256>>>();
    k_prop<<<PROP_BLOCKS, 256>>>(1, ei, ew, eir, ewr);
    k_congru<true><<<PERS, 1024, SM_CG>>>(W_con2, b_con2, W_ih, b_ih,
                                          W_out, b_out, out);
}

// round 11
// speedup vs baseline: 1.7035x; 1.0184x over previous
#include <cuda_runtime.h>
#include <cuda_fp16.h>
#include <math.h>
#include <stdint.h>

#define NN 100000
#define FF 128
#define HH 64
#define CC 16
#define EE 1000000
#define NB 782   // ceil(NN/128)

// word strides (uint32 units), all ≡ 4 (mod 32) for conflict-free lane maps
#define WP128 68   // K=128 fp16 operand row (128 halves + pad)
#define WP64  36   // K=64 fp16 operand row
#define WGH  100   // ghh prefetch row (192 halves + pad)
#define WH0   36   // h0 prefetch row (64 halves + pad)

// ---------------- scratch ----------------------------------------------------
__device__ __align__(16) __half g_h0h[NN * HH];
__device__ __align__(16) __half g_xmidh[NN * HH];
__device__ __align__(16) __half g_ghhh[NN * 192];
__device__ __align__(16) float  g_x1[NN * HH];
__device__ __align__(16) float  g_x2[NN * HH];

// ---------------- helpers -----------------------------------------------------
__device__ __forceinline__ uint32_t f2h2(float a, float b) {
    __half2 h = __floats2half2_rn(a, b);
    return *(uint32_t*)&h;
}
__device__ __forceinline__ float2 h2f2(uint32_t u) {
    return __half22float2(*(__half2*)&u);
}
__device__ __forceinline__ void mma16(float4& d, uint32_t a0, uint32_t a1,
                                      uint32_t a2, uint32_t a3,
                                      uint32_t b0, uint32_t b1) {
    asm volatile(
        "mma.sync.aligned.m16n8k16.row.col.f32.f16.f16.f32 "
        "{%0,%1,%2,%3},{%4,%5,%6,%7},{%8,%9},{%0,%1,%2,%3};"
        : "+f"(d.x), "+f"(d.y), "+f"(d.z), "+f"(d.w)
        : "r"(a0), "r"(a1), "r"(a2), "r"(a3), "r"(b0), "r"(b1));
}
__device__ __forceinline__ float sigf(float x) {
    return 1.f / (1.f + __expf(-x));
}
__device__ __forceinline__ uint32_t smem_u32(const void* p) {
    uint32_t a;
    asm("{ .reg .u64 t; cvta.to.shared.u64 t, %1; cvt.u32.u64 %0, t; }"
        : "=r"(a) : "l"(p));
    return a;
}
#define CP_ASYNC16(dst, src) \
    asm volatile("cp.async.cg.shared.global [%0], [%1], 16;" \
                 :: "r"(dst), "l"(src) : "memory")
#define CP_COMMIT() asm volatile("cp.async.commit_group;" ::: "memory")
#define CP_WAIT0()  asm volatile("cp.async.wait_group 0;" ::: "memory")

// ---------------- zero the two scatter buffers -------------------------------
__global__ void k_zero() {
    const int tot = NN * HH / 4;
    float4 z = make_float4(0.f, 0.f, 0.f, 0.f);
    for (int i = blockIdx.x * blockDim.x + threadIdx.x; i < tot;
         i += gridDim.x * blockDim.x) {
        reinterpret_cast<float4*>(g_x1)[i] = z;
        reinterpret_cast<float4*>(g_x2)[i] = z;
    }
}

// ---------------- persistent k_fg: h0 = x@Wf^T+bf ; ghh = h0@Whh^T+bhh -------
#define FG_A    0                          // 128 x WP128
#define FG_WF   (FG_A + 128 * WP128)       // 64 x WP128
#define FG_WHH  (FG_WF + 64 * WP128)       // 192 x WP64
#define FG_G    (FG_WHH + 192 * WP64)      // 128 x WP64 (h0, fp16)
#define FG_WORDS (FG_G + 128 * WP64)

__global__ __launch_bounds__(1024, 1) void k_fg(const float* __restrict__ x,
                                                const float* __restrict__ Wf,
                                                const float* __restrict__ bf,
                                                const float* __restrict__ Whh,
                                                const float* __restrict__ bhh) {
    extern __shared__ uint32_t sm[];
    uint32_t* sA   = sm + FG_A;
    uint32_t* sWf  = sm + FG_WF;
    uint32_t* sWhh = sm + FG_WHH;
    uint32_t* sG   = sm + FG_G;
    __shared__ float sbf[64];
    __shared__ float sbhh[192];
    int t = threadIdx.x;

    // stage weights ONCE (fp16)
    for (int i = t; i < 64 * 32; i += 1024) {
        int o = i >> 5, q = i & 31;
        float4 v = *(const float4*)(Wf + o * FF + q * 4);
        sWf[o * WP128 + q * 2]     = f2h2(v.x, v.y);
        sWf[o * WP128 + q * 2 + 1] = f2h2(v.z, v.w);
    }
    for (int i = t; i < 192 * 16; i += 1024) {
        int o = i >> 4, q = i & 15;
        float4 v = *(const float4*)(Whh + o * HH + q * 4);
        sWhh[o * WP64 + q * 2]     = f2h2(v.x, v.y);
        sWhh[o * WP64 + q * 2 + 1] = f2h2(v.z, v.w);
    }
    if (t < 64) sbf[t] = bf[t];
    if (t >= 256 && t < 448) sbhh[t - 256] = bhh[t - 256];
    __syncthreads();

    int w = t >> 5, lane = t & 31, g = lane >> 2, tig = lane & 3;
    int r0 = (w & 7) * 16, cw = w >> 3;

    for (int tile = blockIdx.x; tile < NB; tile += gridDim.x) {
        int base = tile * 128;
        for (int i = t; i < 128 * 32; i += 1024) {
            int node = i >> 5, q = i & 31;
            float4 v = make_float4(0.f, 0.f, 0.f, 0.f);
            if (base + node < NN)
                v = *(const float4*)(x + (base + node) * FF + q * 4);
            sA[node * WP128 + q * 2]     = f2h2(v.x, v.y);
            sA[node * WP128 + q * 2 + 1] = f2h2(v.z, v.w);
        }
        __syncthreads();

        // GEMM1: h0 = x @ Wf^T  (K=128, 8 k16 steps, 2 n-tiles/warp)
        {
            int cb = cw * 16;
            float4 acc[2] = {};
#pragma unroll
            for (int s = 0; s < 8; s++) {
                int ko = s * 8;
                uint32_t a0 = sA[(r0 + g) * WP128 + ko + tig];
                uint32_t a1 = sA[(r0 + g + 8) * WP128 + ko + tig];
                uint32_t a2 = sA[(r0 + g) * WP128 + ko + tig + 4];
                uint32_t a3 = sA[(r0 + g + 8) * WP128 + ko + tig + 4];
#pragma unroll
                for (int nt = 0; nt < 2; nt++) {
                    int o = cb + nt * 8 + g;
                    mma16(acc[nt], a0, a1, a2, a3,
                          sWf[o * WP128 + ko + tig], sWf[o * WP128 + ko + tig + 4]);
                }
            }
#pragma unroll
            for (int nt = 0; nt < 2; nt++) {
                int c = cb + nt * 8 + tig * 2;
                int n1 = base + r0 + g, n2 = n1 + 8;
                float v0 = acc[nt].x + sbf[c], v1 = acc[nt].y + sbf[c + 1];
                float v2 = acc[nt].z + sbf[c], v3 = acc[nt].w + sbf[c + 1];
                uint32_t p01 = f2h2(v0, v1), p23 = f2h2(v2, v3);
                if (n1 < NN) *(uint32_t*)(g_h0h + n1 * HH + c) = p01;
                if (n2 < NN) *(uint32_t*)(g_h0h + n2 * HH + c) = p23;
                int cwd = (c >> 1);
                sG[(r0 + g) * WP64 + cwd]     = p01;
                sG[(r0 + g + 8) * WP64 + cwd] = p23;
            }
        }
        __syncthreads();

        // GEMM2: ghh = h0 @ Whh^T  (K=64, 4 k16 steps, 6 n-tiles/warp)
        {
            int cb = cw * 48;
            float4 acc[6] = {};
#pragma unroll
            for (int s = 0; s < 4; s++) {
                int ko = s * 8;
                uint32_t a0 = sG[(r0 + g) * WP64 + ko + tig];
                uint32_t a1 = sG[(r0 + g + 8) * WP64 + ko + tig];
                uint32_t a2 = sG[(r0 + g) * WP64 + ko + tig + 4];
                uint32_t a3 = sG[(r0 + g + 8) * WP64 + ko + tig + 4];
#pragma unroll
                for (int nt = 0; nt < 6; nt++) {
                    int o = cb + nt * 8 + g;
                    mma16(acc[nt], a0, a1, a2, a3,
                          sWhh[o * WP64 + ko + tig], sWhh[o * WP64 + ko + tig + 4]);
                }
            }
#pragma unroll
            for (int nt = 0; nt < 6; nt++) {
                int c = cb + nt * 8 + tig * 2;
                int n1 = base + r0 + g, n2 = n1 + 8;
                if (n1 < NN)
                    *(uint32_t*)(g_ghhh + n1 * 192 + c) =
                        f2h2(acc[nt].x + sbhh[c], acc[nt].y + sbhh[c + 1]);
                if (n2 < NN)
                    *(uint32_t*)(g_ghhh + n2 * 192 + c) =
                        f2h2(acc[nt].z + sbhh[c], acc[nt].w + sbhh[c + 1]);
            }
        }
        __syncthreads();
    }
}

// ---------------- edge propagation: 16 lanes/edge, 4 edges/group -------------
// Contiguous RED.v4 per edge-lane (proven layout); 4 independent gathers in
// flight per thread for MLP.
__global__ __launch_bounds__(256) void k_prop(int use_mid,
                                              const int* __restrict__ ei1,
                                              const float* __restrict__ ew1,
                                              const int* __restrict__ ei2,
                                              const float* __restrict__ ew2) {
    const __half* xin = use_mid ? g_xmidh : g_h0h;
    int group = blockIdx.x * 16 + (threadIdx.x >> 4);
    int l16 = threadIdx.x & 15;
    int slot0 = group * 4;   // quad; never straddles EE (EE % 4 == 0)

    const int* ei;
    const float* ew;
    float* out;
    int e0;
    if (slot0 < EE) { e0 = slot0;      ei = ei1; ew = ew1; out = g_x1; }
    else            { e0 = slot0 - EE; ei = ei2; ew = ew2; out = g_x2; }

    int4   sp = *(const int4*)(ei + e0);        // 4 srcs
    int4   dp = *(const int4*)(ei + EE + e0);   // 4 dsts
    float4 wp = *(const float4*)(ew + e0);      // 4 weights

    // 4 independent LDG.64 gathers (fp16, 4 halves each)
    const __half2* p0 = (const __half2*)(xin + sp.x * HH + l16 * 4);
    const __half2* p1 = (const __half2*)(xin + sp.y * HH + l16 * 4);
    const __half2* p2 = (const __half2*)(xin + sp.z * HH + l16 * 4);
    const __half2* p3 = (const __half2*)(xin + sp.w * HH + l16 * 4);
    __half2 a0 = p0[0], a1 = p0[1];
    __half2 b0 = p1[0], b1 = p1[1];
    __half2 c0 = p2[0], c1 = p2[1];
    __half2 d0 = p3[0], d1 = p3[1];

    float2 fa0 = __half22float2(a0), fa1 = __half22float2(a1);
    float2 fb0 = __half22float2(b0), fb1 = __half22float2(b1);
    float2 fc0 = __half22float2(c0), fc1 = __half22float2(c1);
    float2 fd0 = __half22float2(d0), fd1 = __half22float2(d1);

    float* q0 = out + dp.x * HH + l16 * 4;
    float* q1 = out + dp.y * HH + l16 * 4;
    float* q2 = out + dp.z * HH + l16 * 4;
    float* q3 = out + dp.w * HH + l16 * 4;
    asm volatile("red.global.add.v4.f32 [%0], {%1, %2, %3, %4};"
                 :: "l"(q0), "f"(fa0.x * wp.x), "f"(fa0.y * wp.x),
                    "f"(fa1.x * wp.x), "f"(fa1.y * wp.x) : "memory");
    asm volatile("red.global.add.v4.f32 [%0], {%1, %2, %3, %4};"
                 :: "l"(q1), "f"(fb0.x * wp.y), "f"(fb0.y * wp.y),
                    "f"(fb1.x * wp.y), "f"(fb1.y * wp.y) : "memory");
    asm volatile("red.global.add.v4.f32 [%0], {%1, %2, %3, %4};"
                 :: "l"(q2), "f"(fc0.x * wp.z), "f"(fc0.y * wp.z),
                    "f"(fc1.x * wp.z), "f"(fc1.y * wp.z) : "memory");
    asm volatile("red.global.add.v4.f32 [%0], {%1, %2, %3, %4};"
                 :: "l"(q3), "f"(fd0.x * wp.w), "f"(fd0.y * wp.w),
                    "f"(fd1.x * wp.w), "f"(fd1.y * wp.w) : "memory");
}

// ---------------- persistent fused concat-linear + GRU + out ----------------
#define O_A    0                           // 128 x WP128 (concat, fp16)
#define O_WC   (O_A + 128 * WP128)         // 64 x WP128
#define O_WIH  (O_WC + 64 * WP128)         // 192 x WP64
#define O_WL   (O_WIH + 192 * WP64)        // 64 x WP64
#define O_G    (O_WL + 64 * WP64)          // 128 x WP64 (gg / hnew, fp16)
#define O_GH   (O_G + 128 * WP64)          // 128 x WGH  (ghh prefetch)
#define O_H0   (O_GH + 128 * WGH)          // 128 x WH0  (h0 prefetch)
#define O_BC   (O_H0 + 128 * WH0)
#define O_BIH  (O_BC + 64)
#define O_BL   (O_BIH + 192)
#define O_LY   (O_BL + 64)
#define CG_WORDS (O_LY + 128 * 17)

template <bool FINAL>
__global__ __launch_bounds__(1024, 1) void k_congru(
    const float* __restrict__ Wc,  const float* __restrict__ bc,
    const float* __restrict__ Wih, const float* __restrict__ bih,
    const float* __restrict__ Wl,  const float* __restrict__ bl,
    float* __restrict__ dout) {
    extern __shared__ uint32_t sm[];
    uint32_t* sA   = sm + O_A;
    uint32_t* sWc  = sm + O_WC;
    uint32_t* sWih = sm + O_WIH;
    uint32_t* sWl  = sm + O_WL;
    uint32_t* sG   = sm + O_G;
    uint32_t* sGH  = sm + O_GH;
    uint32_t* sH0  = sm + O_H0;
    float* sbc  = (float*)(sm + O_BC);
    float* sbih = (float*)(sm + O_BIH);
    float* sbl  = (float*)(sm + O_BL);
    float* sLY  = (float*)(sm + O_LY);
    const int OC = FINAL ? CC : HH;

    int t = threadIdx.x;
    uint32_t sGH_b = smem_u32(sGH);
    uint32_t sH0_b = smem_u32(sH0);

    // stage weights ONCE (fp16)
    for (int i = t; i < 64 * 32; i += 1024) {
        int o = i >> 5, q = i & 31;
        float4 v = *(const float4*)(Wc + o * FF + q * 4);
        sWc[o * WP128 + q * 2]     = f2h2(v.x, v.y);
        sWc[o * WP128 + q * 2 + 1] = f2h2(v.z, v.w);
    }
    for (int i = t; i < 192 * 16; i += 1024) {
        int o = i >> 4, q = i & 15;
        float4 v = *(const float4*)(Wih + o * HH + q * 4);
        sWih[o * WP64 + q * 2]     = f2h2(v.x, v.y);
        sWih[o * WP64 + q * 2 + 1] = f2h2(v.z, v.w);
    }
    for (int i = t; i < OC * 16; i += 1024) {
        int o = i >> 4, q = i & 15;
        float4 v = *(const float4*)(Wl + o * HH + q * 4);
        sWl[o * WP64 + q * 2]     = f2h2(v.x, v.y);
        sWl[o * WP64 + q * 2 + 1] = f2h2(v.z, v.w);
    }
    if (t < 64)  sbc[t]  = bc[t];
    if (t < 192) sbih[t] = bih[t];
    if (t < OC)  sbl[t]  = bl[t];
    __syncthreads();

    int w = t >> 5, lane = t & 31, g = lane >> 2, tig = lane & 3;
    int r0 = (w & 7) * 16, cw = w >> 3, cb = cw * 16;

    for (int tile = blockIdx.x; tile < NB; tile += gridDim.x) {
        int base = tile * 128;
        // stage concat input (fp16) + launch ghh/h0 prefetch
        for (int i = t; i < 128 * 16; i += 1024) {
            int node = i >> 4, q = i & 15;
            int n = base + node;
            float4 v1 = make_float4(0.f, 0.f, 0.f, 0.f), v2 = v1;
            if (n < NN) {
                v1 = *(const float4*)(g_x1 + n * HH + q * 4);
                v2 = *(const float4*)(g_x2 + n * HH + q * 4);
            }
            sA[node * WP128 + q * 2]          = f2h2(v1.x, v1.y);
            sA[node * WP128 + q * 2 + 1]      = f2h2(v1.z, v1.w);
            sA[node * WP128 + 32 + q * 2]     = f2h2(v2.x, v2.y);
            sA[node * WP128 + 32 + q * 2 + 1] = f2h2(v2.z, v2.w);
        }
        // ghh: 128 rows x 24 chunks of 16B
        for (int i = t; i < 128 * 24; i += 1024) {
            int row = i / 24, ch = i % 24;
            int n = base + row;
            if (n < NN)
                CP_ASYNC16(sGH_b + (row * WGH + ch * 4) * 4,
                           (const char*)(g_ghhh + n * 192) + ch * 16);
        }
        // h0: 128 rows x 8 chunks of 16B
        for (int i = t; i < 128 * 8; i += 1024) {
            int row = i >> 3, ch = i & 7;
            int n = base + row;
            if (n < NN)
                CP_ASYNC16(sH0_b + (row * WH0 + ch * 4) * 4,
                           (const char*)(g_h0h + n * HH) + ch * 16);
        }
        CP_COMMIT();
        __syncthreads();

        // phase 1: gg = [x1|x2] @ Wc^T + bc  (K=128, 8 k16 steps)
        {
            float4 acc[2] = {};
#pragma unroll
            for (int s = 0; s < 8; s++) {
                int ko = s * 8;
                uint32_t a0 = sA[(r0 + g) * WP128 + ko + tig];
                uint32_t a1 = sA[(r0 + g + 8) * WP128 + ko + tig];
                uint32_t a2 = sA[(r0 + g) * WP128 + ko + tig + 4];
                uint32_t a3 = sA[(r0 + g + 8) * WP128 + ko + tig + 4];
#pragma unroll
                for (int nt = 0; nt < 2; nt++) {
                    int o = cb + nt * 8 + g;
                    mma16(acc[nt], a0, a1, a2, a3,
                          sWc[o * WP128 + ko + tig], sWc[o * WP128 + ko + tig + 4]);
                }
            }
#pragma unroll
            for (int nt = 0; nt < 2; nt++) {
                int c = cb + nt * 8 + tig * 2;
                int cwd = c >> 1;
                sG[(r0 + g) * WP64 + cwd] =
                    f2h2(acc[nt].x + sbc[c], acc[nt].y + sbc[c + 1]);
                sG[(r0 + g + 8) * WP64 + cwd] =
                    f2h2(acc[nt].z + sbc[c], acc[nt].w + sbc[c + 1]);
            }
        }
        __syncthreads();

        // phase 2: gi = gg @ Wih^T  (K=64, 4 k16 steps, 3 gates x 2 nt)
        float4 d2[3][2];
#pragma unroll
        for (int gt = 0; gt < 3; gt++)
#pragma unroll
            for (int nt = 0; nt < 2; nt++)
                d2[gt][nt] = make_float4(0.f, 0.f, 0.f, 0.f);
#pragma unroll
        for (int s = 0; s < 4; s++) {
            int ko = s * 8;
            uint32_t a0 = sG[(r0 + g) * WP64 + ko + tig];
            uint32_t a1 = sG[(r0 + g + 8) * WP64 + ko + tig];
            uint32_t a2 = sG[(r0 + g) * WP64 + ko + tig + 4];
            uint32_t a3 = sG[(r0 + g + 8) * WP64 + ko + tig + 4];
#pragma unroll
            for (int gt = 0; gt < 3; gt++)
#pragma unroll
                for (int nt = 0; nt < 2; nt++) {
                    int o = gt * 64 + cb + nt * 8 + g;
                    mma16(d2[gt][nt], a0, a1, a2, a3,
                          sWih[o * WP64 + ko + tig], sWih[o * WP64 + ko + tig + 4]);
                }
        }

        // prefetched ghh/h0 now needed
        CP_WAIT0();
        __syncthreads();

        // phase 3: GRU elementwise (from prefetched smem)
        float hn[2][4];
#pragma unroll
        for (int nt = 0; nt < 2; nt++) {
            int c = cb + nt * 8 + tig * 2;
            int cwd = c >> 1;
#pragma unroll
            for (int half = 0; half < 2; half++) {
                int nl = r0 + g + half * 8;
                float vr0 = half ? d2[0][nt].z : d2[0][nt].x;
                float vr1 = half ? d2[0][nt].w : d2[0][nt].y;
                float vz0 = half ? d2[1][nt].z : d2[1][nt].x;
                float vz1 = half ? d2[1][nt].w : d2[1][nt].y;
                float vn0 = half ? d2[2][nt].z : d2[2][nt].x;
                float vn1 = half ? d2[2][nt].w : d2[2][nt].y;
                float2 gr = h2f2(sGH[nl * WGH + cwd]);
                float2 gz = h2f2(sGH[nl * WGH + 32 + cwd]);
                float2 gn = h2f2(sGH[nl * WGH + 64 + cwd]);
                float2 h  = h2f2(sH0[nl * WH0 + cwd]);
                float r = sigf(vr0 + sbih[c] + gr.x);
                float z = sigf(vz0 + sbih[64 + c] + gz.x);
                float n = tanhf(vn0 + sbih[128 + c] + r * gn.x);
                hn[nt][half * 2] = (1.f - z) * n + z * h.x;
                r = sigf(vr1 + sbih[c + 1] + gr.y);
                z = sigf(vz1 + sbih[64 + c + 1] + gz.y);
                n = tanhf(vn1 + sbih[128 + c + 1] + r * gn.y);
                hn[nt][half * 2 + 1] = (1.f - z) * n + z * h.y;
            }
        }
        __syncthreads();
#pragma unroll
        for (int nt = 0; nt < 2; nt++) {
            int c = cb + nt * 8 + tig * 2;
            int cwd = c >> 1;
            sG[(r0 + g) * WP64 + cwd]     = f2h2(hn[nt][0], hn[nt][1]);
            sG[(r0 + g + 8) * WP64 + cwd] = f2h2(hn[nt][2], hn[nt][3]);
        }
        __syncthreads();

        // phase 4: output GEMM (K=64, 4 k16 steps)
        if (!FINAL) {
            float4 acc[2] = {};
#pragma unroll
            for (int s = 0; s < 4; s++) {
                int ko = s * 8;
                uint32_t a0 = sG[(r0 + g) * WP64 + ko + tig];
                uint32_t a1 = sG[(r0 + g + 8) * WP64 + ko + tig];
                uint32_t a2 = sG[(r0 + g) * WP64 + ko + tig + 4];
                uint32_t a3 = sG[(r0 + g + 8) * WP64 + ko + tig + 4];
#pragma unroll
                for (int nt = 0; nt < 2; nt++) {
                    int o = cb + nt * 8 + g;
                    mma16(acc[nt], a0, a1, a2, a3,
                          sWl[o * WP64 + ko + tig], sWl[o * WP64 + ko + tig + 4]);
                }
            }
#pragma unroll
            for (int nt = 0; nt < 2; nt++) {
                int c = cb + nt * 8 + tig * 2;
                int n1 = base + r0 + g, n2 = n1 + 8;
                if (n1 < NN)
                    *(uint32_t*)(g_xmidh + n1 * HH + c) =
                        f2h2(acc[nt].x + sbl[c], acc[nt].y + sbl[c + 1]);
                if (n2 < NN)
                    *(uint32_t*)(g_xmidh + n2 * HH + c) =
                        f2h2(acc[nt].z + sbl[c], acc[nt].w + sbl[c + 1]);
            }
        } else {
            if (cw < 2) {
                float4 acc = make_float4(0.f, 0.f, 0.f, 0.f);
                int c0f = cw * 8;
#pragma unroll
                for (int s = 0; s < 4; s++) {
                    int ko = s * 8;
                    uint32_t a0 = sG[(r0 + g) * WP64 + ko + tig];
                    uint32_t a1 = sG[(r0 + g + 8) * WP64 + ko + tig];
                    uint32_t a2 = sG[(r0 + g) * WP64 + ko + tig + 4];
                    uint32_t a3 = sG[(r0 + g + 8) * WP64 + ko + tig + 4];
                    int o = c0f + g;
                    mma16(acc, a0, a1, a2, a3,
                          sWl[o * WP64 + ko + tig], sWl[o * WP64 + ko + tig + 4]);
                }
                int c = c0f + tig * 2;
                sLY[(r0 + g) * 17 + c]         = acc.x + sbl[c];
                sLY[(r0 + g) * 17 + c + 1]     = acc.y + sbl[c + 1];
                sLY[(r0 + g + 8) * 17 + c]     = acc.z + sbl[c];
                sLY[(r0 + g + 8) * 17 + c + 1] = acc.w + sbl[c + 1];
            }
            __syncthreads();
            if (t < 128) {
                int node = base + t;
                if (node < NN) {
                    float m = -1e30f;
#pragma unroll
                    for (int cc = 0; cc < 16; cc++) m = fmaxf(m, sLY[t * 17 + cc]);
                    float s = 0.f;
#pragma unroll
                    for (int cc = 0; cc < 16; cc++) s += expf(sLY[t * 17 + cc] - m);
                    float l = m + logf(s);
#pragma unroll
                    for (int cc = 0; cc < 16; cc++)
                        dout[node * CC + cc] = sLY[t * 17 + cc] - l;
                }
            }
        }
        __syncthreads();
    }
}

// ---------------- launch -----------------------------------------------------
extern "C" void kernel_launch(void* const* d_in, const int* in_sizes, int n_in,
                              void* d_out, int out_size) {
    const float* x       = (const float*)d_in[0];
    const int*   ei      = (const int*)  d_in[1];
    const float* ew      = (const float*)d_in[2];
    const int*   eir     = (const int*)  d_in[3];
    const float* ewr     = (const float*)d_in[4];
    const float* W_first = (const float*)d_in[5];
    const float* b_first = (const float*)d_in[6];
    const float* W_con1  = (const float*)d_in[7];
    const float* b_con1  = (const float*)d_in[8];
    const float* W_con2  = (const float*)d_in[9];
    const float* b_con2  = (const float*)d_in[10];
    const float* W_lin1  = (const float*)d_in[11];
    const float* b_lin1  = (const float*)d_in[12];
    const float* W_out   = (const float*)d_in[13];
    const float* b_out   = (const float*)d_in[14];
    const float* W_ih    = (const float*)d_in[15];
    const float* W_hh    = (const float*)d_in[16];
    const float* b_ih    = (const float*)d_in[17];
    const float* b_hh    = (const float*)d_in[18];
    float* out = (float*)d_out;

    const int SM_FG = FG_WORDS * 4;
    const int SM_CG = CG_WORDS * 4;

    cudaFuncSetAttribute(k_fg, cudaFuncAttributeMaxDynamicSharedMemorySize, SM_FG);
    cudaFuncSetAttribute(k_congru<false>,
                         cudaFuncAttributeMaxDynamicSharedMemorySize, SM_CG);
    cudaFuncSetAttribute(k_congru<true>,
                         cudaFuncAttributeMaxDynamicSharedMemorySize, SM_CG);

    const int PERS = 148;
    const int PROP_BLOCKS = (2 * EE) / 64;   // 4 edges per 16-lane group

    k_zero<<<1024, 256>>>();
    k_fg<<<PERS, 1024, SM_FG>>>(x, W_first, b_first, W_hh, b_hh);
    k_prop<<<PROP_BLOCKS, 256>>>(0, ei, ew, eir, ewr);
    k_congru<false><<<PERS, 1024, SM_CG>>>(W_con1, b_con1, W_ih, b_ih,
                                           W_lin1, b_lin1, nullptr);
    k_zero<<<1024, 256>>>();
    k_prop<<<PROP_BLOCKS, 256>>>(1, ei, ew, eir, ewr);
    k_congru<true><<<PERS, 1024, SM_CG>>>(W_con2, b_con2, W_ih, b_ih,
                                          W_out, b_out, out);
}